// round 7
// baseline (speedup 1.0000x reference)
#include <cuda_runtime.h>
#include <cstdint>
#include <math.h>

#define B_    16
#define CIN   256
#define COUT  256
#define KW    3
#define L_    4096
#define NR    5
#define CK    768            // CIN*KW
#define MROWS 1280           // NR*COUT
#define BL    (B_ * L_)

// ---------------- scratch (device globals; allocation-free) ----------------
__device__ float g_fr[NR * BL];                 // fr[n][b*L+l]
__device__ float g_A[MROWS * CK];               // tf32 weights [rule*COUT+o][ck]
__device__ float g_P[(size_t)B_ * L_ * CK];     // tf32 patches [b][l][ck]

// ---------------- helpers ----------------
__device__ __forceinline__ float to_tf32(float v) {
    uint32_t b;
    asm("cvt.rna.tf32.f32 %0, %1;" : "=r"(b) : "f"(v));
    return __uint_as_float(b);
}
__device__ __forceinline__ uint32_t to_tf32_bits(float v) {
    uint32_t b;
    asm("cvt.rna.tf32.f32 %0, %1;" : "=r"(b) : "f"(v));
    return b;
}
__device__ __forceinline__ void cp16(uint32_t dst, const void* src) {
    asm volatile("cp.async.cg.shared.global [%0], [%1], 16;" :: "r"(dst), "l"(src));
}
__device__ __forceinline__ void cp_commit() {
    asm volatile("cp.async.commit_group;");
}
__device__ __forceinline__ void cp_wait_0() {
    asm volatile("cp.async.wait_group 0;");
}
__device__ __forceinline__ void ldsm4(uint32_t* r, uint32_t addr) {
    asm volatile("ldmatrix.sync.aligned.m8n8.x4.shared.b16 {%0,%1,%2,%3}, [%4];"
                 : "=r"(r[0]), "=r"(r[1]), "=r"(r[2]), "=r"(r[3]) : "r"(addr));
}
__device__ __forceinline__ void mma_tf32(float* d, const uint32_t* a, uint32_t b0, uint32_t b1) {
    asm volatile("mma.sync.aligned.m16n8k8.row.col.f32.tf32.tf32.f32 "
                 "{%0,%1,%2,%3}, {%4,%5,%6,%7}, {%8,%9}, {%0,%1,%2,%3};"
                 : "+f"(d[0]), "+f"(d[1]), "+f"(d[2]), "+f"(d[3])
                 : "r"(a[0]), "r"(a[1]), "r"(a[2]), "r"(a[3]), "r"(b0), "r"(b1));
}

// ---------------------------------------------------------------------------
// prep A: tf32-round weights
// ---------------------------------------------------------------------------
__global__ void __launch_bounds__(256) prepA_kernel(const float* __restrict__ w) {
    int i = blockIdx.x * 256 + threadIdx.x;
    if (i < MROWS * CK) g_A[i] = to_tf32(w[i]);
}

// ---------------------------------------------------------------------------
// prep P: g_P[b][l][ck] = tf32(x[b][ck/3][l + ck%3 - 2]), causal zero-pad
// ---------------------------------------------------------------------------
__global__ void __launch_bounds__(256) prepP_kernel(const float* __restrict__ x) {
    __shared__ float xs[64][34];
    const int tid = threadIdx.x;
    const int l0 = blockIdx.x * 32;
    const int c0 = blockIdx.y * 64;
    const int b  = blockIdx.z;

    for (int idx = tid; idx < 64 * 34; idx += 256) {
        const int c = idx / 34, j = idx % 34;
        const int gl = l0 - 2 + j;
        xs[c][j] = (gl >= 0) ? x[((size_t)(b * CIN + c0 + c)) * L_ + gl] : 0.0f;
    }
    __syncthreads();

    float* Pb = g_P + ((size_t)b * L_ + l0) * CK + c0 * 3;
    for (int idx = tid; idx < 32 * 192; idx += 256) {
        const int li = idx / 192, q = idx % 192;
        const int c = q / 3, k = q - 3 * c;
        Pb[(size_t)li * CK + q] = to_tf32(xs[c][li + k]);
    }
}

// ---------------------------------------------------------------------------
// controller: 4 l per thread, vector loads, full fp32
// ---------------------------------------------------------------------------
__global__ void __launch_bounds__(128) ctrl_kernel(
    const float* __restrict__ x, const float* __restrict__ cw,
    const float* __restrict__ cb)
{
    __shared__ float sw[CK * NR];
    const int tid = threadIdx.x;
    for (int i = tid; i < CK * NR; i += 128) sw[i] = cw[i];
    __syncthreads();

    const int b  = blockIdx.y;
    const int l4 = (blockIdx.x * 128 + tid) * 4;
    const float* xb = x + (size_t)b * CIN * L_;

    float acc[4][NR];
#pragma unroll
    for (int li = 0; li < 4; li++)
#pragma unroll
        for (int n = 0; n < NR; n++) acc[li][n] = cb[n];

    for (int c = 0; c < CIN; c++) {
        const float* xc = xb + (size_t)c * L_ + l4;
        float v[6];
        if (l4 >= 2) {
            const float2 u = *reinterpret_cast<const float2*>(xc - 2);
            v[0] = u.x; v[1] = u.y;
        } else { v[0] = 0.0f; v[1] = 0.0f; }
        const float4 w4 = *reinterpret_cast<const float4*>(xc);
        v[2] = w4.x; v[3] = w4.y; v[4] = w4.z; v[5] = w4.w;

        const float* wr = &sw[c * 3 * NR];
#pragma unroll
        for (int li = 0; li < 4; li++)
#pragma unroll
            for (int n = 0; n < NR; n++)
                acc[li][n] += v[li] * wr[n] + v[li + 1] * wr[NR + n] + v[li + 2] * wr[2 * NR + n];
    }

#pragma unroll
    for (int li = 0; li < 4; li++) {
        float mx = acc[li][0];
#pragma unroll
        for (int n = 1; n < NR; n++) mx = fmaxf(mx, acc[li][n]);
        float e[NR], s = 0.0f;
#pragma unroll
        for (int n = 0; n < NR; n++) { e[n] = __expf(acc[li][n] - mx); s += e[n]; }
        const float inv = 1.0f / s;
        const size_t bl = (size_t)b * L_ + l4 + li;
#pragma unroll
        for (int n = 0; n < NR; n++) g_fr[(size_t)n * BL + bl] = e[n] * inv;
    }
}

// ---------------------------------------------------------------------------
// Fused GEMM+mix, single accumulator: B fragments scaled by fr in registers.
//   out[o,l] = sum_n sum_ck A_n[o,ck] * (fr[l,n] * P[l,ck])  + sum_n fr*bias
// 128 threads (2x2 warps of 64x64), block tile 128x128, 2-stage cp.async,
// XOR-swizzled smem (KROW=32, no pad), 3 blocks/SM.
// ---------------------------------------------------------------------------
#define GBK    32
#define SROWS  256                     // 128 A rows + 128 B rows
#define STAGEF (SROWS * GBK)           // floats per stage (8192)
#define KTILES 24                      // CK / GBK
#define TOTIT  (NR * KTILES)           // 120

__global__ void __launch_bounds__(128, 3) gemm_kernel(
    const float* __restrict__ bias,    // (NR, COUT)
    float* __restrict__ out)           // (B, COUT, L)
{
    extern __shared__ float smem[];
    const uint32_t sbase = (uint32_t)__cvta_generic_to_shared(smem);
    float* sfr = smem + 2 * STAGEF;    // [NR][128] fr slice

    const int tid  = threadIdx.x;
    const int lane = tid & 31;
    const int wid  = tid >> 5;
    const int warp_m = wid >> 1;       // 0..1
    const int warp_n = wid & 1;        // 0..1

    const int b  = blockIdx.z;
    const int o0 = blockIdx.y * 128;
    const int l0 = blockIdx.x * 128;

    const float* Pg = g_P + ((size_t)b * L_ + l0) * CK;

    // fr slice for this l-tile (covered by first in-loop __syncthreads)
    for (int i = tid; i < NR * 128; i += 128) {
        const int n = i >> 7, j = i & 127;
        sfr[i] = g_fr[(size_t)n * BL + (size_t)b * L_ + l0 + j];
    }

    // loader: rows 0..127 = A (o rows of current rule), 128..255 = B (l rows)
    // 2048 16B chunks / 128 threads = 16 per thread. XOR swizzle: chunk^(row&7).
    auto load_tile = [&](int it) {
        const int stage = it & 1;
        const int rule  = it / KTILES;
        const int kt    = (it - rule * KTILES) * GBK;
        const float* Ag = g_A + (size_t)(rule * COUT + o0) * CK + kt;
        const float* Bg = Pg + kt;
        const uint32_t sS = sbase + (uint32_t)(stage * STAGEF) * 4;
#pragma unroll
        for (int i = 0; i < 8; i++) {               // A rows
            const int idx = tid + i * 128;
            const int row = idx >> 3;
            const int c   = idx & 7;
            const uint32_t soff = (uint32_t)(row * GBK + ((c ^ (row & 7)) * 4)) * 4;
            cp16(sS + soff, Ag + (size_t)row * CK + c * 4);
        }
#pragma unroll
        for (int i = 0; i < 8; i++) {               // B rows
            const int idx = tid + i * 128;
            const int row = idx >> 3;               // 0..127 (B-local)
            const int c   = idx & 7;
            const int srow = 128 + row;
            const uint32_t soff = (uint32_t)(srow * GBK + ((c ^ (srow & 7)) * 4)) * 4;
            cp16(sS + soff, Bg + (size_t)row * CK + c * 4);
        }
        cp_commit();
    };

    float acc[4][8][4];                // 64x64 warp tile, single accumulator
#pragma unroll
    for (int mt = 0; mt < 4; mt++)
#pragma unroll
        for (int nt = 0; nt < 8; nt++)
#pragma unroll
            for (int r = 0; r < 4; r++) acc[mt][nt][r] = 0.0f;

    load_tile(0);

    const int arow  = warp_m * 64 + (lane & 15);          // A smem row base
    const int brow  = 128 + warp_n * 64 + (lane & 15);    // B smem row base
    const int lsw   = lane & 7;                            // swizzle key (row&7)
    const int csel  = lane >> 4;                           // 0/1: which 16B of k8
    const int frl   = warp_n * 64 + (lane >> 2);           // b-frag lane l base

    float frv[4][2];                   // fr for b-frag regs, current rule

    for (int it = 0; it < TOTIT; it++) {
        cp_wait_0();
        __syncthreads();               // stage `it` visible; prev reads done
        if (it + 1 < TOTIT) load_tile(it + 1);

        if ((it % KTILES) == 0) {
            const int rule = it / KTILES;
#pragma unroll
            for (int np = 0; np < 4; np++)
#pragma unroll
                for (int h = 0; h < 2; h++)
                    frv[np][h] = sfr[rule * 128 + frl + np * 16 + h * 8];
        }

        const uint32_t sS = sbase + (uint32_t)((it & 1) * STAGEF) * 4;

#pragma unroll
        for (int ks = 0; ks < 4; ks++) {
            const int cidx = ks * 2 + csel;                // chunk 0..7
            uint32_t a[4][4];
#pragma unroll
            for (int mt = 0; mt < 4; mt++) {
                const int row = arow + mt * 16;
                ldsm4(a[mt], sS + (uint32_t)(row * GBK + ((cidx ^ lsw) * 4)) * 4);
            }
            uint32_t bb[4][4];
#pragma unroll
            for (int np = 0; np < 4; np++) {
                const int row = brow + np * 16;
                ldsm4(bb[np], sS + (uint32_t)(row * GBK + ((cidx ^ lsw) * 4)) * 4);
            }
            // scale b-frags by fr (per-lane l = lane>>2 mapping), re-round to tf32
#pragma unroll
            for (int np = 0; np < 4; np++)
#pragma unroll
                for (int j = 0; j < 4; j++)
                    bb[np][j] = to_tf32_bits(__uint_as_float(bb[np][j]) * frv[np][j & 1]);
#pragma unroll
            for (int mt = 0; mt < 4; mt++)
#pragma unroll
                for (int np = 0; np < 4; np++) {
                    mma_tf32(acc[mt][2 * np],     a[mt], bb[np][0], bb[np][2]);
                    mma_tf32(acc[mt][2 * np + 1], a[mt], bb[np][1], bb[np][3]);
                }
        }
        __syncthreads();               // all reads of this stage done before overwrite
    }

    // epilogue: add sum_n fr[l,n]*bias[n,o], write out
    const int obase = o0 + warp_m * 64 + (lane >> 2);
    const int lloc0 = warp_n * 64 + (lane & 3) * 2;
    float* ob = out + ((size_t)b * COUT) * L_ + l0;

#pragma unroll
    for (int mt = 0; mt < 4; mt++) {
        const int o1 = obase + mt * 16;
        const int o2 = o1 + 8;
        float b1[NR], b2[NR];
#pragma unroll
        for (int n = 0; n < NR; n++) {
            b1[n] = __ldg(&bias[n * COUT + o1]);
            b2[n] = __ldg(&bias[n * COUT + o2]);
        }
#pragma unroll
        for (int nt = 0; nt < 8; nt++) {
            const int lloc = lloc0 + nt * 8;
            float t00 = 0.f, t01 = 0.f, t10 = 0.f, t11 = 0.f;
#pragma unroll
            for (int n = 0; n < NR; n++) {
                const float f0 = sfr[n * 128 + lloc];
                const float f1 = sfr[n * 128 + lloc + 1];
                t00 += f0 * b1[n]; t01 += f1 * b1[n];
                t10 += f0 * b2[n]; t11 += f1 * b2[n];
            }
            float2* p0 = reinterpret_cast<float2*>(ob + (size_t)o1 * L_ + lloc);
            float2* p1 = reinterpret_cast<float2*>(ob + (size_t)o2 * L_ + lloc);
            *p0 = make_float2(acc[mt][nt][0] + t00, acc[mt][nt][1] + t01);
            *p1 = make_float2(acc[mt][nt][2] + t10, acc[mt][nt][3] + t11);
        }
    }
}

#define GEMM_SMEM ((2 * STAGEF + NR * 128) * 4)

// ---------------------------------------------------------------------------
// launch
// ---------------------------------------------------------------------------
extern "C" void kernel_launch(void* const* d_in, const int* in_sizes, int n_in,
                              void* d_out, int out_size) {
    const float* x  = (const float*)d_in[0];
    const float* bk = (const float*)d_in[1];
    const float* bb = (const float*)d_in[2];
    const float* cw = (const float*)d_in[3];
    const float* cb = (const float*)d_in[4];
    float* out = (float*)d_out;

    static int smem_set = 0;
    if (!smem_set) {
        cudaFuncSetAttribute(gemm_kernel, cudaFuncAttributeMaxDynamicSharedMemorySize,
                             GEMM_SMEM);
        smem_set = 1;
    }

    prepA_kernel<<<(MROWS * CK + 255) / 256, 256>>>(bk);
    prepP_kernel<<<dim3(L_ / 32, CIN / 64, B_), 256>>>(x);
    ctrl_kernel<<<dim3(L_ / 512, B_), 128>>>(x, cw, cb);
    gemm_kernel<<<dim3(L_ / 128, COUT / 128, B_), 128, GEMM_SMEM>>>(bb, out);
}

// round 11
// speedup vs baseline: 2.1249x; 2.1249x over previous
#include <cuda_runtime.h>
#include <cuda_fp16.h>
#include <cstdint>
#include <math.h>

#define B_    16
#define CIN   256
#define COUT  256
#define L_    4096
#define NR    5
#define KDIM  3840              // NR * 3 * CIN (halves)
#define BL    (B_ * L_)

// ---------------- scratch (device globals; allocation-free) ----------------
__device__ float  g_fr[NR * BL];                                    // fr[n][b*L+l]
__device__ __align__(16) __half g_Ah[COUT * KDIM];                  // [o][(n*3+k)*256+c]
__device__ __align__(16) __half g_XS5h[(size_t)B_ * L_ * KDIM];     // [b][l][kdim] = fr[l]*patch

// ---------------- helpers ----------------
__device__ __forceinline__ void cp16(uint32_t dst, const void* src) {
    asm volatile("cp.async.cg.shared.global [%0], [%1], 16;" :: "r"(dst), "l"(src));
}
__device__ __forceinline__ void cp_commit() { asm volatile("cp.async.commit_group;"); }
__device__ __forceinline__ void cp_wait0()  { asm volatile("cp.async.wait_group 0;"); }
__device__ __forceinline__ void ldsm4(uint32_t* r, uint32_t addr) {
    asm volatile("ldmatrix.sync.aligned.m8n8.x4.shared.b16 {%0,%1,%2,%3}, [%4];"
                 : "=r"(r[0]), "=r"(r[1]), "=r"(r[2]), "=r"(r[3]) : "r"(addr));
}
__device__ __forceinline__ void mma_f16(float* d, const uint32_t* a, uint32_t b0, uint32_t b1) {
    asm volatile("mma.sync.aligned.m16n8k16.row.col.f32.f16.f16.f32 "
                 "{%0,%1,%2,%3}, {%4,%5,%6,%7}, {%8,%9}, {%0,%1,%2,%3};"
                 : "+f"(d[0]), "+f"(d[1]), "+f"(d[2]), "+f"(d[3])
                 : "r"(a[0]), "r"(a[1]), "r"(a[2]), "r"(a[3]), "r"(b0), "r"(b1));
}

// ---------------------------------------------------------------------------
// prep A: g_Ah[o][(n*3+k)*256 + c] = half(bk[n][o][c][k])
// ---------------------------------------------------------------------------
__global__ void __launch_bounds__(256) prepA_kernel(const float* __restrict__ w) {
    int i = blockIdx.x * 256 + threadIdx.x;
    if (i >= COUT * KDIM) return;
    const int o = i / KDIM;
    const int t = i - o * KDIM;
    const int n = t / 768;
    const int rem = t - n * 768;
    const int k = rem >> 8;
    const int c = rem & 255;
    g_Ah[i] = __float2half_rn(w[((n * COUT + o) * CIN + c) * 3 + k]);
}

// ---------------------------------------------------------------------------
// controller: softmax firing strengths (fp32)
// ---------------------------------------------------------------------------
__global__ void __launch_bounds__(128) ctrl_kernel(
    const float* __restrict__ x, const float* __restrict__ cw,
    const float* __restrict__ cb)
{
    __shared__ float sw[768 * NR];
    const int tid = threadIdx.x;
    for (int i = tid; i < 768 * NR; i += 128) sw[i] = cw[i];
    __syncthreads();

    const int b  = blockIdx.y;
    const int l4 = (blockIdx.x * 128 + tid) * 4;
    const float* xb = x + (size_t)b * CIN * L_;

    float acc[4][NR];
#pragma unroll
    for (int li = 0; li < 4; li++)
#pragma unroll
        for (int n = 0; n < NR; n++) acc[li][n] = cb[n];

    for (int c = 0; c < CIN; c++) {
        const float* xc = xb + (size_t)c * L_ + l4;
        float v[6];
        if (l4 >= 2) {
            const float2 u = *reinterpret_cast<const float2*>(xc - 2);
            v[0] = u.x; v[1] = u.y;
        } else { v[0] = 0.0f; v[1] = 0.0f; }
        const float4 w4 = *reinterpret_cast<const float4*>(xc);
        v[2] = w4.x; v[3] = w4.y; v[4] = w4.z; v[5] = w4.w;

        const float* wr = &sw[c * 3 * NR];
#pragma unroll
        for (int li = 0; li < 4; li++)
#pragma unroll
            for (int n = 0; n < NR; n++)
                acc[li][n] += v[li] * wr[n] + v[li + 1] * wr[NR + n] + v[li + 2] * wr[2 * NR + n];
    }

#pragma unroll
    for (int li = 0; li < 4; li++) {
        float mx = acc[li][0];
#pragma unroll
        for (int n = 1; n < NR; n++) mx = fmaxf(mx, acc[li][n]);
        float e[NR], s = 0.0f;
#pragma unroll
        for (int n = 0; n < NR; n++) { e[n] = __expf(acc[li][n] - mx); s += e[n]; }
        const float inv = 1.0f / s;
        const size_t bl = (size_t)b * L_ + l4 + li;
#pragma unroll
        for (int n = 0; n < NR; n++) g_fr[(size_t)n * BL + bl] = e[n] * inv;
    }
}

// ---------------------------------------------------------------------------
// prep XS5: g_XS5h[b][l][(n*3+k)*256+c] = half(fr[n,b,l] * x[b,c,l+k-2])
// (fr taken at the OUTPUT position l — fixes the R9/R10 algebra bug)
// block 256, tile = 128 c x 64 l.
// ---------------------------------------------------------------------------
__global__ void __launch_bounds__(256) prepXS5_kernel(const float* __restrict__ x) {
    __shared__ float xs[128][67];      // x[c][l0-2 .. l0+63]
    __shared__ float frs[NR][64];
    const int tid = threadIdx.x;
    const int l0 = blockIdx.x * 64;
    const int c0 = blockIdx.y * 128;
    const int b  = blockIdx.z;

    for (int idx = tid; idx < 128 * 66; idx += 256) {
        const int c = idx / 66, j = idx - c * 66;
        const int gl = l0 - 2 + j;
        xs[c][j] = (gl >= 0) ? x[((size_t)(b * CIN + c0 + c)) * L_ + gl] : 0.0f;
    }
    for (int i = tid; i < NR * 64; i += 256)
        frs[i >> 6][i & 63] = g_fr[(size_t)(i >> 6) * BL + (size_t)b * L_ + l0 + (i & 63)];
    __syncthreads();

    // each iteration: one (l, channel pair) -> 15 half2 writes (5 rules x 3 taps)
#pragma unroll
    for (int i = 0; i < 16; i++) {
        const int idx = tid + i * 256;
        const int l  = idx >> 6;       // 0..63
        const int c2 = idx & 63;       // channels 2c2, 2c2+1
        float xa[3], xb2[3];
#pragma unroll
        for (int k = 0; k < 3; k++) {
            xa[k]  = xs[2 * c2][l + k];      // x[b, 2c2, l0+l+k-2]
            xb2[k] = xs[2 * c2 + 1][l + k];
        }
        float f[NR];
#pragma unroll
        for (int n = 0; n < NR; n++) f[n] = frs[n][l];

        __half* orow = g_XS5h + ((size_t)b * L_ + l0 + l) * KDIM + c0 + 2 * c2;
#pragma unroll
        for (int n = 0; n < NR; n++)
#pragma unroll
            for (int k = 0; k < 3; k++)
                *reinterpret_cast<__half2*>(orow + (n * 3 + k) * 256) =
                    __floats2half2_rn(f[n] * xa[k], f[n] * xb2[k]);
    }
}

// ---------------------------------------------------------------------------
// fp16 GEMM (+ bias mix epilogue): out(b, 128 o, 128 l), K = 3840 halves.
// 256 threads (2m x 4n warps of 64x32), BK=64, 2-stage cp.async, XOR swizzle.
// Single fp32 accumulator; B rows are per-output-l pre-scaled patches.
// ---------------------------------------------------------------------------
#define BK     64                       // halves per k-tile (128 bytes/row)
#define NTILE  60                       // KDIM / BK
#define A_BYT  (128 * 128)              // 16 KB
#define B_BYT  (128 * 128)              // 16 KB
#define STAGEB (A_BYT + B_BYT)          // 32 KB

__global__ void __launch_bounds__(256, 2) gemm_kernel(
    const float* __restrict__ bias,     // (NR, COUT)
    float* __restrict__ out)            // (B, COUT, L)
{
    extern __shared__ char smem[];
    const uint32_t sb = (uint32_t)__cvta_generic_to_shared(smem);
    float* sfr = reinterpret_cast<float*>(smem + 2 * STAGEB);   // [NR][128]

    const int tid  = threadIdx.x;
    const int lane = tid & 31;
    const int wid  = tid >> 5;
    const int warp_m = wid >> 2;        // 0..1  (64 o rows)
    const int warp_n = wid & 3;         // 0..3  (32 l cols)

    const int b  = blockIdx.z;
    const int o0 = blockIdx.y * 128;
    const int l0 = blockIdx.x * 128;

    // fr slice for the epilogue
    for (int i = tid; i < NR * 128; i += 256) {
        const int n = i >> 7, j = i & 127;
        sfr[i] = g_fr[(size_t)n * BL + (size_t)b * L_ + l0 + j];
    }

    const __half* Bg0 = g_XS5h + ((size_t)b * L_ + l0) * KDIM;

    // loader: A 1024 chunks + B 1024 chunks of 16B; 8 cp16/thread
    auto load_tile = [&](int it) {
        const int s = it & 1;
        const __half* Ag = g_Ah + (size_t)o0 * KDIM + (size_t)it * BK;
        const __half* Bg = Bg0 + (size_t)it * BK;
        const uint32_t sA = sb + s * STAGEB;
        const uint32_t sB = sA + A_BYT;
#pragma unroll
        for (int i = 0; i < 4; i++) {
            const int idx = tid + i * 256;
            const int row = idx >> 3, c = idx & 7;
            cp16(sA + row * 128 + ((c ^ (row & 7)) * 16), Ag + (size_t)row * KDIM + c * 8);
        }
#pragma unroll
        for (int i = 0; i < 4; i++) {
            const int idx = tid + i * 256;
            const int row = idx >> 3, c = idx & 7;
            cp16(sB + row * 128 + ((c ^ (row & 7)) * 16), Bg + (size_t)row * KDIM + c * 8);
        }
        cp_commit();
    };

    float acc[4][4][4];                 // [mt 16o][ng 8l][reg]
#pragma unroll
    for (int mt = 0; mt < 4; mt++)
#pragma unroll
        for (int ng = 0; ng < 4; ng++)
#pragma unroll
            for (int r = 0; r < 4; r++) acc[mt][ng][r] = 0.0f;

    load_tile(0);

    // frag addressing
    const int arow0 = warp_m * 64 + (lane & 15);        // + mt*16
    const int acsel = lane >> 4;                        // 16B chunk select
    const int brow0 = warp_n * 32 + (lane & 7) + ((lane >> 4) << 3);  // + g2*16
    const int bcsel = (lane >> 3) & 1;

    for (int it = 0; it < NTILE; it++) {
        cp_wait0();
        __syncthreads();
        if (it + 1 < NTILE) load_tile(it + 1);

        const uint32_t sA = sb + (it & 1) * STAGEB;
        const uint32_t sB = sA + A_BYT;

#pragma unroll
        for (int ks = 0; ks < 4; ks++) {         // 4 x k16
            uint32_t a[4][4];
#pragma unroll
            for (int mt = 0; mt < 4; mt++) {
                const int row = arow0 + mt * 16;
                const int ch  = (ks * 2 + acsel) ^ (row & 7);
                ldsm4(a[mt], sA + row * 128 + ch * 16);
            }
            uint32_t bb[2][4];
#pragma unroll
            for (int g2 = 0; g2 < 2; g2++) {     // each x4 covers two n8 groups
                const int row = brow0 + g2 * 16;
                const int ch  = (ks * 2 + bcsel) ^ (row & 7);
                ldsm4(bb[g2], sB + row * 128 + ch * 16);
            }
#pragma unroll
            for (int mt = 0; mt < 4; mt++)
#pragma unroll
                for (int g2 = 0; g2 < 2; g2++) {
                    mma_f16(acc[mt][2 * g2],     a[mt], bb[g2][0], bb[g2][1]);
                    mma_f16(acc[mt][2 * g2 + 1], a[mt], bb[g2][2], bb[g2][3]);
                }
        }
        __syncthreads();
    }

    // epilogue: out[o,l] = acc + sum_n fr[n,l] * bias[n,o]
    const int obase = o0 + warp_m * 64 + (lane >> 2);
    const int lloc0 = warp_n * 32 + (lane & 3) * 2;
    float* ob = out + ((size_t)b * COUT) * L_ + l0;

#pragma unroll
    for (int mt = 0; mt < 4; mt++) {
        const int o1 = obase + mt * 16;
        const int o2 = o1 + 8;
        float b1[NR], b2[NR];
#pragma unroll
        for (int n = 0; n < NR; n++) {
            b1[n] = __ldg(&bias[n * COUT + o1]);
            b2[n] = __ldg(&bias[n * COUT + o2]);
        }
#pragma unroll
        for (int ng = 0; ng < 4; ng++) {
            const int lloc = lloc0 + ng * 8;
            float t00 = 0.f, t01 = 0.f, t10 = 0.f, t11 = 0.f;
#pragma unroll
            for (int n = 0; n < NR; n++) {
                const float f0 = sfr[n * 128 + lloc];
                const float f1 = sfr[n * 128 + lloc + 1];
                t00 += f0 * b1[n]; t01 += f1 * b1[n];
                t10 += f0 * b2[n]; t11 += f1 * b2[n];
            }
            float2* p0 = reinterpret_cast<float2*>(ob + (size_t)o1 * L_ + lloc);
            float2* p1 = reinterpret_cast<float2*>(ob + (size_t)o2 * L_ + lloc);
            *p0 = make_float2(acc[mt][ng][0] + t00, acc[mt][ng][1] + t01);
            *p1 = make_float2(acc[mt][ng][2] + t10, acc[mt][ng][3] + t11);
        }
    }
}

#define GEMM_SMEM (2 * STAGEB + NR * 128 * 4)

// ---------------------------------------------------------------------------
// launch
// ---------------------------------------------------------------------------
extern "C" void kernel_launch(void* const* d_in, const int* in_sizes, int n_in,
                              void* d_out, int out_size) {
    const float* x  = (const float*)d_in[0];
    const float* bk = (const float*)d_in[1];
    const float* bb = (const float*)d_in[2];
    const float* cw = (const float*)d_in[3];
    const float* cb = (const float*)d_in[4];
    float* out = (float*)d_out;

    static int smem_set = 0;
    if (!smem_set) {
        cudaFuncSetAttribute(gemm_kernel, cudaFuncAttributeMaxDynamicSharedMemorySize,
                             GEMM_SMEM);
        smem_set = 1;
    }

    prepA_kernel<<<(COUT * KDIM + 255) / 256, 256>>>(bk);
    ctrl_kernel<<<dim3(L_ / 512, B_), 128>>>(x, cw, cb);
    prepXS5_kernel<<<dim3(L_ / 64, CIN / 128, B_), 256>>>(x);
    gemm_kernel<<<dim3(L_ / 128, COUT / 128, B_), 256, GEMM_SMEM>>>(bb, out);
}

// round 12
// speedup vs baseline: 2.1396x; 1.0070x over previous
#include <cuda_runtime.h>
#include <cuda_fp16.h>
#include <cstdint>
#include <math.h>

#define B_    16
#define CIN   256
#define COUT  256
#define L_    4096
#define NR    5
#define KDIM  3840              // NR * 3 * CIN (halves)
#define BL    (B_ * L_)

// ---------------- scratch (device globals; allocation-free) ----------------
__device__ float  g_fr[NR * BL];                                    // fr[n][b*L+l]
__device__ __align__(16) __half g_Ah[COUT * KDIM];                  // [o][(n*3+k)*256+c]
__device__ __align__(16) __half g_XS5h[(size_t)B_ * L_ * KDIM];     // [b][l][kdim] = fr[l]*patch

// ---------------- helpers ----------------
__device__ __forceinline__ void cp16(uint32_t dst, const void* src) {
    asm volatile("cp.async.cg.shared.global [%0], [%1], 16;" :: "r"(dst), "l"(src));
}
__device__ __forceinline__ void cp_commit() { asm volatile("cp.async.commit_group;"); }
__device__ __forceinline__ void ldsm4(uint32_t* r, uint32_t addr) {
    asm volatile("ldmatrix.sync.aligned.m8n8.x4.shared.b16 {%0,%1,%2,%3}, [%4];"
                 : "=r"(r[0]), "=r"(r[1]), "=r"(r[2]), "=r"(r[3]) : "r"(addr));
}
__device__ __forceinline__ void mma_f16(float* d, const uint32_t* a, uint32_t b0, uint32_t b1) {
    asm volatile("mma.sync.aligned.m16n8k16.row.col.f32.f16.f16.f32 "
                 "{%0,%1,%2,%3}, {%4,%5,%6,%7}, {%8,%9}, {%0,%1,%2,%3};"
                 : "+f"(d[0]), "+f"(d[1]), "+f"(d[2]), "+f"(d[3])
                 : "r"(a[0]), "r"(a[1]), "r"(a[2]), "r"(a[3]), "r"(b0), "r"(b1));
}

// ---------------------------------------------------------------------------
// prep A: g_Ah[o][(n*3+k)*256 + c] = half(bk[n][o][c][k])
// ---------------------------------------------------------------------------
__global__ void __launch_bounds__(256) prepA_kernel(const float* __restrict__ w) {
    int i = blockIdx.x * 256 + threadIdx.x;
    if (i >= COUT * KDIM) return;
    const int o = i / KDIM;
    const int t = i - o * KDIM;
    const int n = t / 768;
    const int rem = t - n * 768;
    const int k = rem >> 8;
    const int c = rem & 255;
    g_Ah[i] = __float2half_rn(w[((n * COUT + o) * CIN + c) * 3 + k]);
}

// ---------------------------------------------------------------------------
// controller: softmax firing strengths (fp32)
// ---------------------------------------------------------------------------
__global__ void __launch_bounds__(128) ctrl_kernel(
    const float* __restrict__ x, const float* __restrict__ cw,
    const float* __restrict__ cb)
{
    __shared__ float sw[768 * NR];
    const int tid = threadIdx.x;
    for (int i = tid; i < 768 * NR; i += 128) sw[i] = cw[i];
    __syncthreads();

    const int b  = blockIdx.y;
    const int l4 = (blockIdx.x * 128 + tid) * 4;
    const float* xb = x + (size_t)b * CIN * L_;

    float acc[4][NR];
#pragma unroll
    for (int li = 0; li < 4; li++)
#pragma unroll
        for (int n = 0; n < NR; n++) acc[li][n] = cb[n];

    for (int c = 0; c < CIN; c++) {
        const float* xc = xb + (size_t)c * L_ + l4;
        float v[6];
        if (l4 >= 2) {
            const float2 u = *reinterpret_cast<const float2*>(xc - 2);
            v[0] = u.x; v[1] = u.y;
        } else { v[0] = 0.0f; v[1] = 0.0f; }
        const float4 w4 = *reinterpret_cast<const float4*>(xc);
        v[2] = w4.x; v[3] = w4.y; v[4] = w4.z; v[5] = w4.w;

        const float* wr = &sw[c * 3 * NR];
#pragma unroll
        for (int li = 0; li < 4; li++)
#pragma unroll
            for (int n = 0; n < NR; n++)
                acc[li][n] += v[li] * wr[n] + v[li + 1] * wr[NR + n] + v[li + 2] * wr[2 * NR + n];
    }

#pragma unroll
    for (int li = 0; li < 4; li++) {
        float mx = acc[li][0];
#pragma unroll
        for (int n = 1; n < NR; n++) mx = fmaxf(mx, acc[li][n]);
        float e[NR], s = 0.0f;
#pragma unroll
        for (int n = 0; n < NR; n++) { e[n] = __expf(acc[li][n] - mx); s += e[n]; }
        const float inv = 1.0f / s;
        const size_t bl = (size_t)b * L_ + l4 + li;
#pragma unroll
        for (int n = 0; n < NR; n++) g_fr[(size_t)n * BL + bl] = e[n] * inv;
    }
}

// ---------------------------------------------------------------------------
// prep XS5: g_XS5h[b][l][(n*3+k)*256+c] = half(fr[n,b,l] * x[b,c,l+k-2])
// Vectorized: each (l, 8-channel group) unit emits 15 x 16B stores.
// block 256, tile = 128 c x 64 l.
// ---------------------------------------------------------------------------
__global__ void __launch_bounds__(256) prepXS5_kernel(const float* __restrict__ x) {
    __shared__ float xs[128][67];      // x[c][l0-2 .. l0+63]
    __shared__ float frs[NR][64];
    const int tid = threadIdx.x;
    const int l0 = blockIdx.x * 64;
    const int c0 = blockIdx.y * 128;
    const int b  = blockIdx.z;

    for (int idx = tid; idx < 128 * 66; idx += 256) {
        const int c = idx / 66, j = idx - c * 66;
        const int gl = l0 - 2 + j;
        xs[c][j] = (gl >= 0) ? x[((size_t)(b * CIN + c0 + c)) * L_ + gl] : 0.0f;
    }
    for (int i = tid; i < NR * 64; i += 256)
        frs[i >> 6][i & 63] = g_fr[(size_t)(i >> 6) * BL + (size_t)b * L_ + l0 + (i & 63)];
    __syncthreads();

    // 64 l x 16 c-groups (8 channels each) = 1024 units, 4 per thread
#pragma unroll
    for (int u = 0; u < 4; u++) {
        const int idx = tid + u * 256;
        const int l = idx >> 4;        // 0..63
        const int g = idx & 15;        // channels c0+8g .. +7
        float f[NR];
#pragma unroll
        for (int n = 0; n < NR; n++) f[n] = frs[n][l];
        float xv[3][8];
#pragma unroll
        for (int k = 0; k < 3; k++)
#pragma unroll
            for (int cc = 0; cc < 8; cc++) xv[k][cc] = xs[8 * g + cc][l + k];

        __half* orow = g_XS5h + ((size_t)b * L_ + l0 + l) * KDIM + c0 + 8 * g;
#pragma unroll
        for (int n = 0; n < NR; n++)
#pragma unroll
            for (int k = 0; k < 3; k++) {
                const float fn = f[n];
                __half2 h0 = __floats2half2_rn(fn * xv[k][0], fn * xv[k][1]);
                __half2 h1 = __floats2half2_rn(fn * xv[k][2], fn * xv[k][3]);
                __half2 h2 = __floats2half2_rn(fn * xv[k][4], fn * xv[k][5]);
                __half2 h3 = __floats2half2_rn(fn * xv[k][6], fn * xv[k][7]);
                uint4 pkt;
                pkt.x = *reinterpret_cast<uint32_t*>(&h0);
                pkt.y = *reinterpret_cast<uint32_t*>(&h1);
                pkt.z = *reinterpret_cast<uint32_t*>(&h2);
                pkt.w = *reinterpret_cast<uint32_t*>(&h3);
                *reinterpret_cast<uint4*>(orow + (n * 3 + k) * 256) = pkt;
            }
    }
}

// ---------------------------------------------------------------------------
// fp16 GEMM (+ bias mix epilogue): out(b, 128 o, 128 l), K = 3840 halves.
// 256 threads (2m x 4n warps of 64x32), BK=64, 3-stage cp.async ring
// (wait_group 1, one commit per iteration), XOR swizzle.
// ---------------------------------------------------------------------------
#define BK     64                       // halves per k-tile (128 bytes/row)
#define NTILE  60                       // KDIM / BK
#define A_BYT  (128 * 128)              // 16 KB
#define B_BYT  (128 * 128)              // 16 KB
#define STAGEB (A_BYT + B_BYT)          // 32 KB
#define NST    3

__global__ void __launch_bounds__(256, 2) gemm_kernel(
    const float* __restrict__ bias,     // (NR, COUT)
    float* __restrict__ out)            // (B, COUT, L)
{
    extern __shared__ char smem[];
    const uint32_t sb = (uint32_t)__cvta_generic_to_shared(smem);
    float* sfr = reinterpret_cast<float*>(smem + NST * STAGEB);   // [NR][128]

    const int tid  = threadIdx.x;
    const int lane = tid & 31;
    const int wid  = tid >> 5;
    const int warp_m = wid >> 2;        // 0..1  (64 o rows)
    const int warp_n = wid & 3;         // 0..3  (32 l cols)

    const int b  = blockIdx.z;
    const int o0 = blockIdx.y * 128;
    const int l0 = blockIdx.x * 128;

    // fr slice for the epilogue
    for (int i = tid; i < NR * 128; i += 256) {
        const int n = i >> 7, j = i & 127;
        sfr[i] = g_fr[(size_t)n * BL + (size_t)b * L_ + l0 + j];
    }

    const __half* Bg0 = g_XS5h + ((size_t)b * L_ + l0) * KDIM;

    // loader: A 1024 chunks + B 1024 chunks of 16B; 8 cp16/thread
    auto load_tile = [&](int it) {
        const int s = it % NST;
        const __half* Ag = g_Ah + (size_t)o0 * KDIM + (size_t)it * BK;
        const __half* Bg = Bg0 + (size_t)it * BK;
        const uint32_t sA = sb + s * STAGEB;
        const uint32_t sB = sA + A_BYT;
#pragma unroll
        for (int i = 0; i < 4; i++) {
            const int idx = tid + i * 256;
            const int row = idx >> 3, c = idx & 7;
            cp16(sA + row * 128 + ((c ^ (row & 7)) * 16), Ag + (size_t)row * KDIM + c * 8);
        }
#pragma unroll
        for (int i = 0; i < 4; i++) {
            const int idx = tid + i * 256;
            const int row = idx >> 3, c = idx & 7;
            cp16(sB + row * 128 + ((c ^ (row & 7)) * 16), Bg + (size_t)row * KDIM + c * 8);
        }
        cp_commit();
    };

    float acc[4][4][4];                 // [mt 16o][ng 8l][reg]
#pragma unroll
    for (int mt = 0; mt < 4; mt++)
#pragma unroll
        for (int ng = 0; ng < 4; ng++)
#pragma unroll
            for (int r = 0; r < 4; r++) acc[mt][ng][r] = 0.0f;

    // prologue: two stages in flight
    load_tile(0);
    load_tile(1);

    // frag addressing
    const int arow0 = warp_m * 64 + (lane & 15);        // + mt*16
    const int acsel = lane >> 4;                        // 16B chunk select
    const int brow0 = warp_n * 32 + (lane & 7) + ((lane >> 4) << 3);  // + g2*16
    const int bcsel = (lane >> 3) & 1;

    for (int it = 0; it < NTILE; it++) {
        asm volatile("cp.async.wait_group 1;");   // tile `it` complete
        __syncthreads();                          // all warps past iter it-1 reads

        // exactly one commit group per iteration
        if (it + 2 < NTILE) load_tile(it + 2);
        else cp_commit();

        const uint32_t sA = sb + (it % NST) * STAGEB;
        const uint32_t sB = sA + A_BYT;

#pragma unroll
        for (int ks = 0; ks < 4; ks++) {         // 4 x k16
            uint32_t a[4][4];
#pragma unroll
            for (int mt = 0; mt < 4; mt++) {
                const int row = arow0 + mt * 16;
                const int ch  = (ks * 2 + acsel) ^ (row & 7);
                ldsm4(a[mt], sA + row * 128 + ch * 16);
            }
            uint32_t bb[2][4];
#pragma unroll
            for (int g2 = 0; g2 < 2; g2++) {     // each x4 covers two n8 groups
                const int row = brow0 + g2 * 16;
                const int ch  = (ks * 2 + bcsel) ^ (row & 7);
                ldsm4(bb[g2], sB + row * 128 + ch * 16);
            }
#pragma unroll
            for (int mt = 0; mt < 4; mt++)
#pragma unroll
                for (int g2 = 0; g2 < 2; g2++) {
                    mma_f16(acc[mt][2 * g2],     a[mt], bb[g2][0], bb[g2][1]);
                    mma_f16(acc[mt][2 * g2 + 1], a[mt], bb[g2][2], bb[g2][3]);
                }
        }
    }

    // epilogue: out[o,l] = acc + sum_n fr[n,l] * bias[n,o]
    const int obase = o0 + warp_m * 64 + (lane >> 2);
    const int lloc0 = warp_n * 32 + (lane & 3) * 2;
    float* ob = out + ((size_t)b * COUT) * L_ + l0;

#pragma unroll
    for (int mt = 0; mt < 4; mt++) {
        const int o1 = obase + mt * 16;
        const int o2 = o1 + 8;
        float b1[NR], b2[NR];
#pragma unroll
        for (int n = 0; n < NR; n++) {
            b1[n] = __ldg(&bias[n * COUT + o1]);
            b2[n] = __ldg(&bias[n * COUT + o2]);
        }
#pragma unroll
        for (int ng = 0; ng < 4; ng++) {
            const int lloc = lloc0 + ng * 8;
            float t00 = 0.f, t01 = 0.f, t10 = 0.f, t11 = 0.f;
#pragma unroll
            for (int n = 0; n < NR; n++) {
                const float f0 = sfr[n * 128 + lloc];
                const float f1 = sfr[n * 128 + lloc + 1];
                t00 += f0 * b1[n]; t01 += f1 * b1[n];
                t10 += f0 * b2[n]; t11 += f1 * b2[n];
            }
            float2* p0 = reinterpret_cast<float2*>(ob + (size_t)o1 * L_ + lloc);
            float2* p1 = reinterpret_cast<float2*>(ob + (size_t)o2 * L_ + lloc);
            *p0 = make_float2(acc[mt][ng][0] + t00, acc[mt][ng][1] + t01);
            *p1 = make_float2(acc[mt][ng][2] + t10, acc[mt][ng][3] + t11);
        }
    }
}

#define GEMM_SMEM (NST * STAGEB + NR * 128 * 4)

// ---------------------------------------------------------------------------
// launch
// ---------------------------------------------------------------------------
extern "C" void kernel_launch(void* const* d_in, const int* in_sizes, int n_in,
                              void* d_out, int out_size) {
    const float* x  = (const float*)d_in[0];
    const float* bk = (const float*)d_in[1];
    const float* bb = (const float*)d_in[2];
    const float* cw = (const float*)d_in[3];
    const float* cb = (const float*)d_in[4];
    float* out = (float*)d_out;

    static int smem_set = 0;
    if (!smem_set) {
        cudaFuncSetAttribute(gemm_kernel, cudaFuncAttributeMaxDynamicSharedMemorySize,
                             GEMM_SMEM);
        smem_set = 1;
    }

    prepA_kernel<<<(COUT * KDIM + 255) / 256, 256>>>(bk);
    ctrl_kernel<<<dim3(L_ / 512, B_), 128>>>(x, cw, cb);
    prepXS5_kernel<<<dim3(L_ / 64, CIN / 128, B_), 256>>>(x);
    gemm_kernel<<<dim3(L_ / 128, COUT / 128, B_), 256, GEMM_SMEM>>>(bb, out);
}

// round 13
// speedup vs baseline: 2.3017x; 1.0757x over previous
#include <cuda_runtime.h>
#include <cuda_fp16.h>
#include <cstdint>
#include <math.h>

#define B_    16
#define CIN   256
#define COUT  256
#define L_    4096
#define LP2   (L_ + 2)          // 2 leading zero rows (causal pad)
#define NR    5
#define KDIM  3840              // NR * 3 * CIN (halves)
#define BL    (B_ * L_)

// ---------------- scratch (device globals; allocation-free) ----------------
__device__ float  g_fr[NR * BL];                                 // fr[n][b*L+l]
__device__ __align__(16) __half g_Ah[COUT * KDIM];               // [o][(n*3+k)*256+c]
__device__ __align__(16) __half g_xth[(size_t)B_ * LP2 * CIN];   // [b][l+2][c] = half(x)

// ---------------- helpers ----------------
__device__ __forceinline__ void cp16(uint32_t dst, const void* src) {
    asm volatile("cp.async.cg.shared.global [%0], [%1], 16;" :: "r"(dst), "l"(src));
}
__device__ __forceinline__ void cp_commit() { asm volatile("cp.async.commit_group;"); }
__device__ __forceinline__ void ldsm4(uint32_t* r, uint32_t addr) {
    asm volatile("ldmatrix.sync.aligned.m8n8.x4.shared.b16 {%0,%1,%2,%3}, [%4];"
                 : "=r"(r[0]), "=r"(r[1]), "=r"(r[2]), "=r"(r[3]) : "r"(addr));
}
__device__ __forceinline__ void mma_f16(float* d, const uint32_t* a, uint32_t b0, uint32_t b1) {
    asm volatile("mma.sync.aligned.m16n8k16.row.col.f32.f16.f16.f32 "
                 "{%0,%1,%2,%3}, {%4,%5,%6,%7}, {%8,%9}, {%0,%1,%2,%3};"
                 : "+f"(d[0]), "+f"(d[1]), "+f"(d[2]), "+f"(d[3])
                 : "r"(a[0]), "r"(a[1]), "r"(a[2]), "r"(a[3]), "r"(b0), "r"(b1));
}

// ---------------------------------------------------------------------------
// prep A: g_Ah[o][(n*3+k)*256 + c] = half(bk[n][o][c][k])
// ---------------------------------------------------------------------------
__global__ void __launch_bounds__(256) prepA_kernel(const float* __restrict__ w) {
    int i = blockIdx.x * 256 + threadIdx.x;
    if (i >= COUT * KDIM) return;
    const int o = i / KDIM;
    const int t = i - o * KDIM;
    const int n = t / 768;
    const int rem = t - n * 768;
    const int k = rem >> 8;
    const int c = rem & 255;
    g_Ah[i] = __float2half_rn(w[((n * COUT + o) * CIN + c) * 3 + k]);
}

// ---------------------------------------------------------------------------
// prep XT: g_xth[b][2+l][c] = half(x[b][c][l]); rows 0,1 zeroed.
// block 256, tile = 64 c x 64 l.
// ---------------------------------------------------------------------------
__global__ void __launch_bounds__(256) prepXT_kernel(const float* __restrict__ x) {
    __shared__ float xs[64][65];
    const int tid = threadIdx.x;
    const int l0 = blockIdx.x * 64;
    const int c0 = blockIdx.y * 64;
    const int b  = blockIdx.z;

    for (int i = tid; i < 64 * 64; i += 256) {
        const int c = i >> 6, l = i & 63;
        xs[c][l] = x[((size_t)(b * CIN + c0 + c)) * L_ + l0 + l];
    }
    __syncthreads();

    for (int i = tid; i < 64 * 32; i += 256) {      // half2 over c
        const int l = i >> 5, c2 = i & 31;
        __half2 h = __floats2half2_rn(xs[2 * c2][l], xs[2 * c2 + 1][l]);
        *reinterpret_cast<__half2*>(
            &g_xth[((size_t)b * LP2 + 2 + l0 + l) * CIN + c0 + 2 * c2]) = h;
    }
    // zero causal-pad rows 0,1 for this c-range
    if (blockIdx.x == 0 && tid < 64) {
        const int r = tid >> 5, c2 = tid & 31;
        *reinterpret_cast<__half2*>(
            &g_xth[((size_t)b * LP2 + r) * CIN + c0 + 2 * c2]) = __floats2half2_rn(0.f, 0.f);
    }
}

// ---------------------------------------------------------------------------
// controller: softmax firing strengths (fp32)
// ---------------------------------------------------------------------------
__global__ void __launch_bounds__(128) ctrl_kernel(
    const float* __restrict__ x, const float* __restrict__ cw,
    const float* __restrict__ cb)
{
    __shared__ float sw[768 * NR];
    const int tid = threadIdx.x;
    for (int i = tid; i < 768 * NR; i += 128) sw[i] = cw[i];
    __syncthreads();

    const int b  = blockIdx.y;
    const int l4 = (blockIdx.x * 128 + tid) * 4;
    const float* xb = x + (size_t)b * CIN * L_;

    float acc[4][NR];
#pragma unroll
    for (int li = 0; li < 4; li++)
#pragma unroll
        for (int n = 0; n < NR; n++) acc[li][n] = cb[n];

    for (int c = 0; c < CIN; c++) {
        const float* xc = xb + (size_t)c * L_ + l4;
        float v[6];
        if (l4 >= 2) {
            const float2 u = *reinterpret_cast<const float2*>(xc - 2);
            v[0] = u.x; v[1] = u.y;
        } else { v[0] = 0.0f; v[1] = 0.0f; }
        const float4 w4 = *reinterpret_cast<const float4*>(xc);
        v[2] = w4.x; v[3] = w4.y; v[4] = w4.z; v[5] = w4.w;

        const float* wr = &sw[c * 3 * NR];
#pragma unroll
        for (int li = 0; li < 4; li++)
#pragma unroll
            for (int n = 0; n < NR; n++)
                acc[li][n] += v[li] * wr[n] + v[li + 1] * wr[NR + n] + v[li + 2] * wr[2 * NR + n];
    }

#pragma unroll
    for (int li = 0; li < 4; li++) {
        float mx = acc[li][0];
#pragma unroll
        for (int n = 1; n < NR; n++) mx = fmaxf(mx, acc[li][n]);
        float e[NR], s = 0.0f;
#pragma unroll
        for (int n = 0; n < NR; n++) { e[n] = __expf(acc[li][n] - mx); s += e[n]; }
        const float inv = 1.0f / s;
        const size_t bl = (size_t)b * L_ + l4 + li;
#pragma unroll
        for (int n = 0; n < NR; n++) g_fr[(size_t)n * BL + bl] = e[n] * inv;
    }
}

// ---------------------------------------------------------------------------
// fp16 GEMM (+ fr on b-frags + bias mix epilogue): out(b, 128 o, 128 l).
// K = 3840; kt it covers rule n=it/12, tap k=(it%12)>>2, c0=(it%4)*64.
// B tile = rows of g_xth at l+k (unfold = addressing); fr applied to
// b-fragments via HMUL2 (per-lane dup, reloaded once per rule).
// 256 threads (2m x 4n warps of 64x32), 3-stage cp.async, XOR swizzle.
// ---------------------------------------------------------------------------
#define BK     64                       // halves per k-tile (128 bytes/row)
#define NTILE  60                       // KDIM / BK
#define A_BYT  (128 * 128)              // 16 KB
#define B_BYT  (128 * 128)              // 16 KB
#define STAGEB (A_BYT + B_BYT)          // 32 KB
#define NST    3

__global__ void __launch_bounds__(256, 2) gemm_kernel(
    const float* __restrict__ bias,     // (NR, COUT)
    float* __restrict__ out)            // (B, COUT, L)
{
    extern __shared__ char smem[];
    const uint32_t sb = (uint32_t)__cvta_generic_to_shared(smem);
    float* sfr = reinterpret_cast<float*>(smem + NST * STAGEB);   // [NR][128]

    const int tid  = threadIdx.x;
    const int lane = tid & 31;
    const int wid  = tid >> 5;
    const int warp_m = wid >> 2;        // 0..1  (64 o rows)
    const int warp_n = wid & 3;         // 0..3  (32 l cols)

    const int b  = blockIdx.z;
    const int o0 = blockIdx.y * 128;
    const int l0 = blockIdx.x * 128;

    // fr slice (fp32) for b-frag scaling and epilogue
    for (int i = tid; i < NR * 128; i += 256) {
        const int n = i >> 7, j = i & 127;
        sfr[i] = g_fr[(size_t)n * BL + (size_t)b * L_ + l0 + j];
    }

    const __half* Xt0 = g_xth + ((size_t)b * LP2 + l0) * CIN;

    // loader: A 1024 chunks + B 1024 chunks of 16B; 8 cp16/thread
    auto load_tile = [&](int it) {
        const int s = it % NST;
        const int n = it / 12;
        const int r = it - 12 * n;
        const int k = r >> 2;
        const int c0q = (r & 3) * 64;
        const __half* Ag = g_Ah + (size_t)o0 * KDIM + (size_t)it * BK;
        const __half* Bg = Xt0 + (size_t)k * CIN + c0q;   // row l adds l*CIN
        const uint32_t sA = sb + s * STAGEB;
        const uint32_t sB = sA + A_BYT;
#pragma unroll
        for (int i = 0; i < 4; i++) {
            const int idx = tid + i * 256;
            const int row = idx >> 3, c = idx & 7;
            cp16(sA + row * 128 + ((c ^ (row & 7)) * 16), Ag + (size_t)row * KDIM + c * 8);
        }
#pragma unroll
        for (int i = 0; i < 4; i++) {
            const int idx = tid + i * 256;
            const int row = idx >> 3, c = idx & 7;
            cp16(sB + row * 128 + ((c ^ (row & 7)) * 16), Bg + (size_t)row * CIN + c * 8);
        }
        cp_commit();
    };

    float acc[4][4][4];                 // [mt 16o][ng 8l][reg]
#pragma unroll
    for (int mt = 0; mt < 4; mt++)
#pragma unroll
        for (int ng = 0; ng < 4; ng++)
#pragma unroll
            for (int r = 0; r < 4; r++) acc[mt][ng][r] = 0.0f;

    // prologue: two stages in flight
    load_tile(0);
    load_tile(1);

    // frag addressing
    const int arow0 = warp_m * 64 + (lane & 15);        // + mt*16
    const int acsel = lane >> 4;                        // 16B chunk select
    const int brow0 = warp_n * 32 + (lane & 7) + ((lane >> 4) << 3);  // + g2*16
    const int bcsel = (lane >> 3) & 1;
    const int frcol = warp_n * 32 + (lane >> 2);        // + q*8

    __half2 frh[4];                     // fr dup for the 4 n8 groups, current rule

    for (int it = 0; it < NTILE; it++) {
        asm volatile("cp.async.wait_group 1;");   // tile `it` complete
        __syncthreads();                          // all warps past iter it-1 reads

        if (it + 2 < NTILE) load_tile(it + 2);
        else cp_commit();                         // keep one group per iteration

        if ((it % 12) == 0) {                     // rule boundary: reload fr
            const int n = it / 12;
#pragma unroll
            for (int q = 0; q < 4; q++)
                frh[q] = __half2half2(__float2half_rn(sfr[n * 128 + frcol + q * 8]));
        }

        const uint32_t sA = sb + (it % NST) * STAGEB;
        const uint32_t sB = sA + A_BYT;

#pragma unroll
        for (int ks = 0; ks < 4; ks++) {         // 4 x k16
            uint32_t a[4][4];
#pragma unroll
            for (int mt = 0; mt < 4; mt++) {
                const int row = arow0 + mt * 16;
                const int ch  = (ks * 2 + acsel) ^ (row & 7);
                ldsm4(a[mt], sA + row * 128 + ch * 16);
            }
            uint32_t bb[2][4];
#pragma unroll
            for (int g2 = 0; g2 < 2; g2++) {
                const int row = brow0 + g2 * 16;
                const int ch  = (ks * 2 + bcsel) ^ (row & 7);
                ldsm4(bb[g2], sB + row * 128 + ch * 16);
            }
            // scale b-frags by fr (each reg = 2 k-halves of ONE column l)
#pragma unroll
            for (int g2 = 0; g2 < 2; g2++)
#pragma unroll
                for (int j = 0; j < 4; j++) {
                    __half2 v = *reinterpret_cast<__half2*>(&bb[g2][j]);
                    v = __hmul2(v, frh[2 * g2 + (j >> 1)]);
                    bb[g2][j] = *reinterpret_cast<uint32_t*>(&v);
                }
#pragma unroll
            for (int mt = 0; mt < 4; mt++)
#pragma unroll
                for (int g2 = 0; g2 < 2; g2++) {
                    mma_f16(acc[mt][2 * g2],     a[mt], bb[g2][0], bb[g2][1]);
                    mma_f16(acc[mt][2 * g2 + 1], a[mt], bb[g2][2], bb[g2][3]);
                }
        }
    }

    // epilogue: out[o,l] = acc + sum_n fr[n,l] * bias[n,o]
    const int obase = o0 + warp_m * 64 + (lane >> 2);
    const int lloc0 = warp_n * 32 + (lane & 3) * 2;
    float* ob = out + ((size_t)b * COUT) * L_ + l0;

#pragma unroll
    for (int mt = 0; mt < 4; mt++) {
        const int o1 = obase + mt * 16;
        const int o2 = o1 + 8;
        float b1[NR], b2[NR];
#pragma unroll
        for (int n = 0; n < NR; n++) {
            b1[n] = __ldg(&bias[n * COUT + o1]);
            b2[n] = __ldg(&bias[n * COUT + o2]);
        }
#pragma unroll
        for (int ng = 0; ng < 4; ng++) {
            const int lloc = lloc0 + ng * 8;
            float t00 = 0.f, t01 = 0.f, t10 = 0.f, t11 = 0.f;
#pragma unroll
            for (int n = 0; n < NR; n++) {
                const float f0 = sfr[n * 128 + lloc];
                const float f1 = sfr[n * 128 + lloc + 1];
                t00 += f0 * b1[n]; t01 += f1 * b1[n];
                t10 += f0 * b2[n]; t11 += f1 * b2[n];
            }
            float2* p0 = reinterpret_cast<float2*>(ob + (size_t)o1 * L_ + lloc);
            float2* p1 = reinterpret_cast<float2*>(ob + (size_t)o2 * L_ + lloc);
            *p0 = make_float2(acc[mt][ng][0] + t00, acc[mt][ng][1] + t01);
            *p1 = make_float2(acc[mt][ng][2] + t10, acc[mt][ng][3] + t11);
        }
    }
}

#define GEMM_SMEM (NST * STAGEB + NR * 128 * 4)

// ---------------------------------------------------------------------------
// launch
// ---------------------------------------------------------------------------
extern "C" void kernel_launch(void* const* d_in, const int* in_sizes, int n_in,
                              void* d_out, int out_size) {
    const float* x  = (const float*)d_in[0];
    const float* bk = (const float*)d_in[1];
    const float* bb = (const float*)d_in[2];
    const float* cw = (const float*)d_in[3];
    const float* cb = (const float*)d_in[4];
    float* out = (float*)d_out;

    static int smem_set = 0;
    if (!smem_set) {
        cudaFuncSetAttribute(gemm_kernel, cudaFuncAttributeMaxDynamicSharedMemorySize,
                             GEMM_SMEM);
        smem_set = 1;
    }

    prepA_kernel<<<(COUT * KDIM + 255) / 256, 256>>>(bk);
    prepXT_kernel<<<dim3(L_ / 64, CIN / 64, B_), 256>>>(x);
    ctrl_kernel<<<dim3(L_ / 512, B_), 128>>>(x, cw, cb);
    gemm_kernel<<<dim3(L_ / 128, COUT / 128, B_), 256, GEMM_SMEM>>>(bb, out);
}

// round 14
// speedup vs baseline: 3.0910x; 1.3430x over previous
#include <cuda_runtime.h>
#include <cuda_fp16.h>
#include <cstdint>
#include <math.h>

#define B_    16
#define CIN   256
#define COUT  256
#define L_    4096
#define LP2   (L_ + 2)          // 2 leading zero rows (causal pad)
#define NR    5
#define KDIM  3840              // NR * 3 * CIN (halves)
#define BL    (B_ * L_)

// ---------------- scratch (device globals; allocation-free) ----------------
__device__ float  g_fr[NR * BL];                                 // fr[n][b*L+l]
__device__ __align__(16) __half g_Ah[COUT * KDIM];               // [o][(n*3+k)*256+c]
__device__ __align__(16) __half g_xth[(size_t)B_ * LP2 * CIN];   // [b][l+2][c] = half(x)

// ---------------- helpers ----------------
__device__ __forceinline__ void cp16(uint32_t dst, const void* src) {
    asm volatile("cp.async.cg.shared.global [%0], [%1], 16;" :: "r"(dst), "l"(src));
}
__device__ __forceinline__ void cp_commit() { asm volatile("cp.async.commit_group;"); }
__device__ __forceinline__ void ldsm4(uint32_t* r, uint32_t addr) {
    asm volatile("ldmatrix.sync.aligned.m8n8.x4.shared.b16 {%0,%1,%2,%3}, [%4];"
                 : "=r"(r[0]), "=r"(r[1]), "=r"(r[2]), "=r"(r[3]) : "r"(addr));
}
__device__ __forceinline__ void mma_f16(float* d, const uint32_t* a, uint32_t b0, uint32_t b1) {
    asm volatile("mma.sync.aligned.m16n8k16.row.col.f32.f16.f16.f32 "
                 "{%0,%1,%2,%3}, {%4,%5,%6,%7}, {%8,%9}, {%0,%1,%2,%3};"
                 : "+f"(d[0]), "+f"(d[1]), "+f"(d[2]), "+f"(d[3])
                 : "r"(a[0]), "r"(a[1]), "r"(a[2]), "r"(a[3]), "r"(b0), "r"(b1));
}

// ---------------------------------------------------------------------------
// prep A: g_Ah[o][(n*3+k)*256 + c] = half(bk[n][o][c][k])
// ---------------------------------------------------------------------------
__global__ void __launch_bounds__(256) prepA_kernel(const float* __restrict__ w) {
    int i = blockIdx.x * 256 + threadIdx.x;
    if (i >= COUT * KDIM) return;
    const int o = i / KDIM;
    const int t = i - o * KDIM;
    const int n = t / 768;
    const int rem = t - n * 768;
    const int k = rem >> 8;
    const int c = rem & 255;
    g_Ah[i] = __float2half_rn(w[((n * COUT + o) * CIN + c) * 3 + k]);
}

// ---------------------------------------------------------------------------
// FUSED prep: one pass over x produces
//   (a) g_xth[b][2+l][c] = half(x[b][c][l])          (transpose)
//   (b) g_fr[n][b*L+l]   = softmax_n(ctrl logits)    (controller)
// grid (L/64, B), block 256. Chunks of 64 channels; per-thread partial
// logits over 16 channels; smem reduce of the 4 chunk-subpartials.
// ---------------------------------------------------------------------------
__global__ void __launch_bounds__(256) prep_fused_kernel(
    const float* __restrict__ x, const float* __restrict__ cw,
    const float* __restrict__ cb)
{
    __shared__ float sw[768 * NR];       // full ctrl weights (15 KB)
    __shared__ float xs[64][66];         // chunk: 64 c x (l0-2 .. l0+63)
    __shared__ float part[4][64][NR];    // per-(chunk-subgroup, l) partials

    const int tid = threadIdx.x;
    const int l0  = blockIdx.x * 64;
    const int b   = blockIdx.y;

    for (int i = tid; i < 768 * NR; i += 256) sw[i] = cw[i];

    const int lt = tid & 63;             // reduction lane: l within tile
    const int cg = tid >> 6;             // 0..3 : 16-channel subgroup
    float acc[NR];
#pragma unroll
    for (int n = 0; n < NR; n++) acc[n] = 0.0f;

    for (int cc = 0; cc < 4; cc++) {     // 4 chunks of 64 channels
        __syncthreads();                 // xs reusable (prev chunk done)
        // load chunk: 64 rows x 66 cols
        for (int i = tid; i < 64 * 66; i += 256) {
            const int c = i / 66, j = i - c * 66;
            const int gl = l0 - 2 + j;
            xs[c][j] = (gl >= 0)
                ? x[((size_t)(b * CIN + cc * 64 + c)) * L_ + gl] : 0.0f;
        }
        __syncthreads();

        // (a) transposed half write: g_xth[b][2+l0+l][cc*64 + 2*c2 ..]
        for (int i = tid; i < 64 * 32; i += 256) {
            const int l = i >> 5, c2 = i & 31;
            __half2 h = __floats2half2_rn(xs[2 * c2][l + 2], xs[2 * c2 + 1][l + 2]);
            *reinterpret_cast<__half2*>(
                &g_xth[((size_t)b * LP2 + 2 + l0 + l) * CIN + cc * 64 + 2 * c2]) = h;
        }

        // (b) controller partials: 16 channels per thread
#pragma unroll
        for (int ci = 0; ci < 16; ci++) {
            const int c  = cg * 16 + ci;
            const int gc = cc * 64 + c;
            const float x0 = xs[c][lt];
            const float x1 = xs[c][lt + 1];
            const float x2 = xs[c][lt + 2];
            const float* w0 = &sw[(gc * 3 + 0) * NR];
#pragma unroll
            for (int n = 0; n < NR; n++)
                acc[n] += x0 * w0[n] + x1 * w0[NR + n] + x2 * w0[2 * NR + n];
        }
    }

#pragma unroll
    for (int n = 0; n < NR; n++) part[cg][lt][n] = acc[n];
    __syncthreads();

    // reduce + softmax (one thread per l)
    if (tid < 64) {
        const int l = tid;
        float s[NR];
#pragma unroll
        for (int n = 0; n < NR; n++)
            s[n] = part[0][l][n] + part[1][l][n] + part[2][l][n] + part[3][l][n]
                 + __ldg(&cb[n]);
        float mx = s[0];
#pragma unroll
        for (int n = 1; n < NR; n++) mx = fmaxf(mx, s[n]);
        float e[NR], sum = 0.0f;
#pragma unroll
        for (int n = 0; n < NR; n++) { e[n] = __expf(s[n] - mx); sum += e[n]; }
        const float inv = 1.0f / sum;
        const size_t bl = (size_t)b * L_ + l0 + l;
#pragma unroll
        for (int n = 0; n < NR; n++) g_fr[(size_t)n * BL + bl] = e[n] * inv;
    }

    // zero the 2 causal-pad rows of g_xth (once, l0 == 0 blocks)
    if (blockIdx.x == 0 && tid < 256) {
        const int r = tid >> 7, c2 = tid & 127;
        *reinterpret_cast<__half2*>(
            &g_xth[((size_t)b * LP2 + r) * CIN + 2 * c2]) = __floats2half2_rn(0.f, 0.f);
    }
}

// ---------------------------------------------------------------------------
// fp16 GEMM (+ fr on b-frags + bias mix epilogue): out(b, 128 o, 128 l).
// K = 3840; kt it covers rule n=it/12, tap k=(it%12)>>2, c0=(it%4)*64.
// B tile = rows of g_xth at l+k (unfold = addressing); fr applied to
// b-fragments via HMUL2. 256 threads (2x4 warps of 64x32), 3-stage ring.
// ---------------------------------------------------------------------------
#define BK     64
#define NTILE  60
#define A_BYT  (128 * 128)
#define B_BYT  (128 * 128)
#define STAGEB (A_BYT + B_BYT)
#define NST    3

__global__ void __launch_bounds__(256, 2) gemm_kernel(
    const float* __restrict__ bias,     // (NR, COUT)
    float* __restrict__ out)            // (B, COUT, L)
{
    extern __shared__ char smem[];
    const uint32_t sb = (uint32_t)__cvta_generic_to_shared(smem);
    float* sfr = reinterpret_cast<float*>(smem + NST * STAGEB);   // [NR][128]

    const int tid  = threadIdx.x;
    const int lane = tid & 31;
    const int wid  = tid >> 5;
    const int warp_m = wid >> 2;
    const int warp_n = wid & 3;

    const int b  = blockIdx.z;
    const int o0 = blockIdx.y * 128;
    const int l0 = blockIdx.x * 128;

    for (int i = tid; i < NR * 128; i += 256) {
        const int n = i >> 7, j = i & 127;
        sfr[i] = g_fr[(size_t)n * BL + (size_t)b * L_ + l0 + j];
    }

    const __half* Xt0 = g_xth + ((size_t)b * LP2 + l0) * CIN;

    auto load_tile = [&](int it) {
        const int s = it % NST;
        const int n = it / 12;
        const int r = it - 12 * n;
        const int k = r >> 2;
        const int c0q = (r & 3) * 64;
        const __half* Ag = g_Ah + (size_t)o0 * KDIM + (size_t)it * BK;
        const __half* Bg = Xt0 + (size_t)k * CIN + c0q;
        const uint32_t sA = sb + s * STAGEB;
        const uint32_t sB = sA + A_BYT;
#pragma unroll
        for (int i = 0; i < 4; i++) {
            const int idx = tid + i * 256;
            const int row = idx >> 3, c = idx & 7;
            cp16(sA + row * 128 + ((c ^ (row & 7)) * 16), Ag + (size_t)row * KDIM + c * 8);
        }
#pragma unroll
        for (int i = 0; i < 4; i++) {
            const int idx = tid + i * 256;
            const int row = idx >> 3, c = idx & 7;
            cp16(sB + row * 128 + ((c ^ (row & 7)) * 16), Bg + (size_t)row * CIN + c * 8);
        }
        cp_commit();
    };

    float acc[4][4][4];
#pragma unroll
    for (int mt = 0; mt < 4; mt++)
#pragma unroll
        for (int ng = 0; ng < 4; ng++)
#pragma unroll
            for (int r = 0; r < 4; r++) acc[mt][ng][r] = 0.0f;

    load_tile(0);
    load_tile(1);

    const int arow0 = warp_m * 64 + (lane & 15);
    const int acsel = lane >> 4;
    const int brow0 = warp_n * 32 + (lane & 7) + ((lane >> 4) << 3);
    const int bcsel = (lane >> 3) & 1;
    const int frcol = warp_n * 32 + (lane >> 2);

    __half2 frh[4];

    for (int it = 0; it < NTILE; it++) {
        asm volatile("cp.async.wait_group 1;");
        __syncthreads();

        if (it + 2 < NTILE) load_tile(it + 2);
        else cp_commit();

        if ((it % 12) == 0) {
            const int n = it / 12;
#pragma unroll
            for (int q = 0; q < 4; q++)
                frh[q] = __half2half2(__float2half_rn(sfr[n * 128 + frcol + q * 8]));
        }

        const uint32_t sA = sb + (it % NST) * STAGEB;
        const uint32_t sB = sA + A_BYT;

#pragma unroll
        for (int ks = 0; ks < 4; ks++) {
            uint32_t a[4][4];
#pragma unroll
            for (int mt = 0; mt < 4; mt++) {
                const int row = arow0 + mt * 16;
                const int ch  = (ks * 2 + acsel) ^ (row & 7);
                ldsm4(a[mt], sA + row * 128 + ch * 16);
            }
            uint32_t bb[2][4];
#pragma unroll
            for (int g2 = 0; g2 < 2; g2++) {
                const int row = brow0 + g2 * 16;
                const int ch  = (ks * 2 + bcsel) ^ (row & 7);
                ldsm4(bb[g2], sB + row * 128 + ch * 16);
            }
#pragma unroll
            for (int g2 = 0; g2 < 2; g2++)
#pragma unroll
                for (int j = 0; j < 4; j++) {
                    __half2 v = *reinterpret_cast<__half2*>(&bb[g2][j]);
                    v = __hmul2(v, frh[2 * g2 + (j >> 1)]);
                    bb[g2][j] = *reinterpret_cast<uint32_t*>(&v);
                }
#pragma unroll
            for (int mt = 0; mt < 4; mt++)
#pragma unroll
                for (int g2 = 0; g2 < 2; g2++) {
                    mma_f16(acc[mt][2 * g2],     a[mt], bb[g2][0], bb[g2][1]);
                    mma_f16(acc[mt][2 * g2 + 1], a[mt], bb[g2][2], bb[g2][3]);
                }
        }
    }

    // epilogue
    const int obase = o0 + warp_m * 64 + (lane >> 2);
    const int lloc0 = warp_n * 32 + (lane & 3) * 2;
    float* ob = out + ((size_t)b * COUT) * L_ + l0;

#pragma unroll
    for (int mt = 0; mt < 4; mt++) {
        const int o1 = obase + mt * 16;
        const int o2 = o1 + 8;
        float b1[NR], b2[NR];
#pragma unroll
        for (int n = 0; n < NR; n++) {
            b1[n] = __ldg(&bias[n * COUT + o1]);
            b2[n] = __ldg(&bias[n * COUT + o2]);
        }
#pragma unroll
        for (int ng = 0; ng < 4; ng++) {
            const int lloc = lloc0 + ng * 8;
            float t00 = 0.f, t01 = 0.f, t10 = 0.f, t11 = 0.f;
#pragma unroll
            for (int n = 0; n < NR; n++) {
                const float f0 = sfr[n * 128 + lloc];
                const float f1 = sfr[n * 128 + lloc + 1];
                t00 += f0 * b1[n]; t01 += f1 * b1[n];
                t10 += f0 * b2[n]; t11 += f1 * b2[n];
            }
            float2* p0 = reinterpret_cast<float2*>(ob + (size_t)o1 * L_ + lloc);
            float2* p1 = reinterpret_cast<float2*>(ob + (size_t)o2 * L_ + lloc);
            *p0 = make_float2(acc[mt][ng][0] + t00, acc[mt][ng][1] + t01);
            *p1 = make_float2(acc[mt][ng][2] + t10, acc[mt][ng][3] + t11);
        }
    }
}

#define GEMM_SMEM (NST * STAGEB + NR * 128 * 4)

// ---------------------------------------------------------------------------
// launch
// ---------------------------------------------------------------------------
extern "C" void kernel_launch(void* const* d_in, const int* in_sizes, int n_in,
                              void* d_out, int out_size) {
    const float* x  = (const float*)d_in[0];
    const float* bk = (const float*)d_in[1];
    const float* bb = (const float*)d_in[2];
    const float* cw = (const float*)d_in[3];
    const float* cb = (const float*)d_in[4];
    float* out = (float*)d_out;

    static int smem_set = 0;
    if (!smem_set) {
        cudaFuncSetAttribute(gemm_kernel, cudaFuncAttributeMaxDynamicSharedMemorySize,
                             GEMM_SMEM);
        smem_set = 1;
    }

    prepA_kernel<<<(COUT * KDIM + 255) / 256, 256>>>(bk);
    prep_fused_kernel<<<dim3(L_ / 64, B_), 256>>>(x, cw, cb);
    gemm_kernel<<<dim3(L_ / 128, COUT / 128, B_), 256, GEMM_SMEM>>>(bb, out);
}

// round 15
// speedup vs baseline: 3.1235x; 1.0105x over previous
#include <cuda_runtime.h>
#include <cuda_fp16.h>
#include <cstdint>
#include <math.h>

#define B_    16
#define CIN   256
#define COUT  256
#define L_    4096
#define LP2   (L_ + 2)          // 2 leading zero rows (causal pad)
#define NR    5
#define KDIM  3840              // NR * 3 * CIN (halves)
#define BL    (B_ * L_)

// ---------------- scratch (device globals; allocation-free) ----------------
__device__ float  g_fr[NR * BL];                                 // fr[n][b*L+l]
__device__ __align__(16) __half g_Ah[COUT * KDIM];               // [o][(n*3+k)*256+c]
__device__ __align__(16) __half g_xth[(size_t)B_ * LP2 * CIN];   // [b][l+2][c] = half(x)

// ---------------- helpers ----------------
__device__ __forceinline__ void cp16(uint32_t dst, const void* src) {
    asm volatile("cp.async.cg.shared.global [%0], [%1], 16;" :: "r"(dst), "l"(src));
}
__device__ __forceinline__ void cp_commit() { asm volatile("cp.async.commit_group;"); }
__device__ __forceinline__ void ldsm4(uint32_t* r, uint32_t addr) {
    asm volatile("ldmatrix.sync.aligned.m8n8.x4.shared.b16 {%0,%1,%2,%3}, [%4];"
                 : "=r"(r[0]), "=r"(r[1]), "=r"(r[2]), "=r"(r[3]) : "r"(addr));
}
__device__ __forceinline__ void mma_f16(float* d, const uint32_t* a, uint32_t b0, uint32_t b1) {
    asm volatile("mma.sync.aligned.m16n8k16.row.col.f32.f16.f16.f32 "
                 "{%0,%1,%2,%3}, {%4,%5,%6,%7}, {%8,%9}, {%0,%1,%2,%3};"
                 : "+f"(d[0]), "+f"(d[1]), "+f"(d[2]), "+f"(d[3])
                 : "r"(a[0]), "r"(a[1]), "r"(a[2]), "r"(a[3]), "r"(b0), "r"(b1));
}

// ---------------------------------------------------------------------------
// prep A: g_Ah[o][(n*3+k)*256 + c] = half(bk[n][o][c][k])
// ---------------------------------------------------------------------------
__global__ void __launch_bounds__(256) prepA_kernel(const float* __restrict__ w) {
    int i = blockIdx.x * 256 + threadIdx.x;
    if (i >= COUT * KDIM) return;
    const int o = i / KDIM;
    const int t = i - o * KDIM;
    const int n = t / 768;
    const int rem = t - n * 768;
    const int k = rem >> 8;
    const int c = rem & 255;
    g_Ah[i] = __float2half_rn(w[((n * COUT + o) * CIN + c) * 3 + k]);
}

// ---------------------------------------------------------------------------
// FUSED prep v2 (512 threads, 2 rounds of 128 channels):
//   (a) g_xth[b][2+l][c] = half(x[b][c][l])          (transpose)
//   (b) g_fr[n][b*L+l]   = softmax_n(ctrl logits)    (controller)
// grid (L/64, B). Dynamic smem: sw 15K | xs 128x66 33K | part 8x64xNR 10K.
// ---------------------------------------------------------------------------
#define PREP_SW    (768 * NR)                    // 3840 floats
#define PREP_XS    (128 * 66)                    // 8448 floats
#define PREP_PART  (8 * 64 * NR)                 // 2560 floats
#define PREP_SMEM  ((PREP_SW + PREP_XS + PREP_PART) * 4)

__global__ void __launch_bounds__(512) prep_fused_kernel(
    const float* __restrict__ x, const float* __restrict__ cw,
    const float* __restrict__ cb)
{
    extern __shared__ float psm[];
    float* sw   = psm;                     // [3840]
    float* xs   = sw + PREP_SW;            // [128][66]
    float* part = xs + PREP_XS;            // [cg][l][n]

    const int tid = threadIdx.x;
    const int l0  = blockIdx.x * 64;
    const int b   = blockIdx.y;

    for (int i = tid; i < PREP_SW; i += 512) sw[i] = cw[i];

    const int lt = tid & 63;               // l within tile
    const int cg = tid >> 6;               // 0..7 : 16-channel subgroup
    float acc[NR];
#pragma unroll
    for (int n = 0; n < NR; n++) acc[n] = 0.0f;

#pragma unroll
    for (int cc = 0; cc < 2; cc++) {       // 2 rounds of 128 channels
        __syncthreads();                   // xs reusable (and sw ready, rnd 0)
        for (int i = tid; i < 128 * 66; i += 512) {
            const int c = i / 66, j = i - c * 66;
            const int gl = l0 - 2 + j;
            xs[c * 66 + j] = (gl >= 0)
                ? x[((size_t)(b * CIN + cc * 128 + c)) * L_ + gl] : 0.0f;
        }
        __syncthreads();

        // (a) transposed half writes: 64 l x 64 half2 (128 c) = 4096 / 512 = 8
        for (int i = tid; i < 64 * 64; i += 512) {
            const int l = i >> 6, c2 = i & 63;
            __half2 h = __floats2half2_rn(xs[(2 * c2) * 66 + l + 2],
                                          xs[(2 * c2 + 1) * 66 + l + 2]);
            *reinterpret_cast<__half2*>(
                &g_xth[((size_t)b * LP2 + 2 + l0 + l) * CIN + cc * 128 + 2 * c2]) = h;
        }

        // (b) controller partials: 16 channels per thread
#pragma unroll
        for (int ci = 0; ci < 16; ci++) {
            const int c  = cg * 16 + ci;
            const int gc = cc * 128 + c;
            const float x0 = xs[c * 66 + lt];
            const float x1 = xs[c * 66 + lt + 1];
            const float x2 = xs[c * 66 + lt + 2];
            const float* w0 = &sw[gc * 3 * NR];
#pragma unroll
            for (int n = 0; n < NR; n++)
                acc[n] += x0 * w0[n] + x1 * w0[NR + n] + x2 * w0[2 * NR + n];
        }
    }

#pragma unroll
    for (int n = 0; n < NR; n++) part[(cg * 64 + lt) * NR + n] = acc[n];
    __syncthreads();

    // reduce + softmax (one thread per l)
    if (tid < 64) {
        const int l = tid;
        float s[NR];
#pragma unroll
        for (int n = 0; n < NR; n++) {
            float t = __ldg(&cb[n]);
#pragma unroll
            for (int g = 0; g < 8; g++) t += part[(g * 64 + l) * NR + n];
            s[n] = t;
        }
        float mx = s[0];
#pragma unroll
        for (int n = 1; n < NR; n++) mx = fmaxf(mx, s[n]);
        float e[NR], sum = 0.0f;
#pragma unroll
        for (int n = 0; n < NR; n++) { e[n] = __expf(s[n] - mx); sum += e[n]; }
        const float inv = 1.0f / sum;
        const size_t bl = (size_t)b * L_ + l0 + l;
#pragma unroll
        for (int n = 0; n < NR; n++) g_fr[(size_t)n * BL + bl] = e[n] * inv;
    }

    // zero the 2 causal-pad rows of g_xth (once, l0 == 0 blocks)
    if (blockIdx.x == 0 && tid < 256) {
        const int r = tid >> 7, c2 = tid & 127;
        *reinterpret_cast<__half2*>(
            &g_xth[((size_t)b * LP2 + r) * CIN + 2 * c2]) = __floats2half2_rn(0.f, 0.f);
    }
}

// ---------------------------------------------------------------------------
// fp16 GEMM (+ fr on b-frags + bias mix epilogue): out(b, 128 o, 128 l).
// UNCHANGED from Round 13/14 (307 us, tensor 69.7%).
// ---------------------------------------------------------------------------
#define BK     64
#define NTILE  60
#define A_BYT  (128 * 128)
#define B_BYT  (128 * 128)
#define STAGEB (A_BYT + B_BYT)
#define NST    3

__global__ void __launch_bounds__(256, 2) gemm_kernel(
    const float* __restrict__ bias,     // (NR, COUT)
    float* __restrict__ out)            // (B, COUT, L)
{
    extern __shared__ char smem[];
    const uint32_t sb = (uint32_t)__cvta_generic_to_shared(smem);
    float* sfr = reinterpret_cast<float*>(smem + NST * STAGEB);   // [NR][128]

    const int tid  = threadIdx.x;
    const int lane = tid & 31;
    const int wid  = tid >> 5;
    const int warp_m = wid >> 2;
    const int warp_n = wid & 3;

    const int b  = blockIdx.z;
    const int o0 = blockIdx.y * 128;
    const int l0 = blockIdx.x * 128;

    for (int i = tid; i < NR * 128; i += 256) {
        const int n = i >> 7, j = i & 127;
        sfr[i] = g_fr[(size_t)n * BL + (size_t)b * L_ + l0 + j];
    }

    const __half* Xt0 = g_xth + ((size_t)b * LP2 + l0) * CIN;

    auto load_tile = [&](int it) {
        const int s = it % NST;
        const int n = it / 12;
        const int r = it - 12 * n;
        const int k = r >> 2;
        const int c0q = (r & 3) * 64;
        const __half* Ag = g_Ah + (size_t)o0 * KDIM + (size_t)it * BK;
        const __half* Bg = Xt0 + (size_t)k * CIN + c0q;
        const uint32_t sA = sb + s * STAGEB;
        const uint32_t sB = sA + A_BYT;
#pragma unroll
        for (int i = 0; i < 4; i++) {
            const int idx = tid + i * 256;
            const int row = idx >> 3, c = idx & 7;
            cp16(sA + row * 128 + ((c ^ (row & 7)) * 16), Ag + (size_t)row * KDIM + c * 8);
        }
#pragma unroll
        for (int i = 0; i < 4; i++) {
            const int idx = tid + i * 256;
            const int row = idx >> 3, c = idx & 7;
            cp16(sB + row * 128 + ((c ^ (row & 7)) * 16), Bg + (size_t)row * CIN + c * 8);
        }
        cp_commit();
    };

    float acc[4][4][4];
#pragma unroll
    for (int mt = 0; mt < 4; mt++)
#pragma unroll
        for (int ng = 0; ng < 4; ng++)
#pragma unroll
            for (int r = 0; r < 4; r++) acc[mt][ng][r] = 0.0f;

    load_tile(0);
    load_tile(1);

    const int arow0 = warp_m * 64 + (lane & 15);
    const int acsel = lane >> 4;
    const int brow0 = warp_n * 32 + (lane & 7) + ((lane >> 4) << 3);
    const int bcsel = (lane >> 3) & 1;
    const int frcol = warp_n * 32 + (lane >> 2);

    __half2 frh[4];

    for (int it = 0; it < NTILE; it++) {
        asm volatile("cp.async.wait_group 1;");
        __syncthreads();

        if (it + 2 < NTILE) load_tile(it + 2);
        else cp_commit();

        if ((it % 12) == 0) {
            const int n = it / 12;
#pragma unroll
            for (int q = 0; q < 4; q++)
                frh[q] = __half2half2(__float2half_rn(sfr[n * 128 + frcol + q * 8]));
        }

        const uint32_t sA = sb + (it % NST) * STAGEB;
        const uint32_t sB = sA + A_BYT;

#pragma unroll
        for (int ks = 0; ks < 4; ks++) {
            uint32_t a[4][4];
#pragma unroll
            for (int mt = 0; mt < 4; mt++) {
                const int row = arow0 + mt * 16;
                const int ch  = (ks * 2 + acsel) ^ (row & 7);
                ldsm4(a[mt], sA + row * 128 + ch * 16);
            }
            uint32_t bb[2][4];
#pragma unroll
            for (int g2 = 0; g2 < 2; g2++) {
                const int row = brow0 + g2 * 16;
                const int ch  = (ks * 2 + bcsel) ^ (row & 7);
                ldsm4(bb[g2], sB + row * 128 + ch * 16);
            }
#pragma unroll
            for (int g2 = 0; g2 < 2; g2++)
#pragma unroll
                for (int j = 0; j < 4; j++) {
                    __half2 v = *reinterpret_cast<__half2*>(&bb[g2][j]);
                    v = __hmul2(v, frh[2 * g2 + (j >> 1)]);
                    bb[g2][j] = *reinterpret_cast<uint32_t*>(&v);
                }
#pragma unroll
            for (int mt = 0; mt < 4; mt++)
#pragma unroll
                for (int g2 = 0; g2 < 2; g2++) {
                    mma_f16(acc[mt][2 * g2],     a[mt], bb[g2][0], bb[g2][1]);
                    mma_f16(acc[mt][2 * g2 + 1], a[mt], bb[g2][2], bb[g2][3]);
                }
        }
    }

    // epilogue
    const int obase = o0 + warp_m * 64 + (lane >> 2);
    const int lloc0 = warp_n * 32 + (lane & 3) * 2;
    float* ob = out + ((size_t)b * COUT) * L_ + l0;

#pragma unroll
    for (int mt = 0; mt < 4; mt++) {
        const int o1 = obase + mt * 16;
        const int o2 = o1 + 8;
        float b1[NR], b2[NR];
#pragma unroll
        for (int n = 0; n < NR; n++) {
            b1[n] = __ldg(&bias[n * COUT + o1]);
            b2[n] = __ldg(&bias[n * COUT + o2]);
        }
#pragma unroll
        for (int ng = 0; ng < 4; ng++) {
            const int lloc = lloc0 + ng * 8;
            float t00 = 0.f, t01 = 0.f, t10 = 0.f, t11 = 0.f;
#pragma unroll
            for (int n = 0; n < NR; n++) {
                const float f0 = sfr[n * 128 + lloc];
                const float f1 = sfr[n * 128 + lloc + 1];
                t00 += f0 * b1[n]; t01 += f1 * b1[n];
                t10 += f0 * b2[n]; t11 += f1 * b2[n];
            }
            float2* p0 = reinterpret_cast<float2*>(ob + (size_t)o1 * L_ + lloc);
            float2* p1 = reinterpret_cast<float2*>(ob + (size_t)o2 * L_ + lloc);
            *p0 = make_float2(acc[mt][ng][0] + t00, acc[mt][ng][1] + t01);
            *p1 = make_float2(acc[mt][ng][2] + t10, acc[mt][ng][3] + t11);
        }
    }
}

#define GEMM_SMEM (NST * STAGEB + NR * 128 * 4)

// ---------------------------------------------------------------------------
// launch
// ---------------------------------------------------------------------------
extern "C" void kernel_launch(void* const* d_in, const int* in_sizes, int n_in,
                              void* d_out, int out_size) {
    const float* x  = (const float*)d_in[0];
    const float* bk = (const float*)d_in[1];
    const float* bb = (const float*)d_in[2];
    const float* cw = (const float*)d_in[3];
    const float* cb = (const float*)d_in[4];
    float* out = (float*)d_out;

    static int smem_set = 0;
    if (!smem_set) {
        cudaFuncSetAttribute(gemm_kernel, cudaFuncAttributeMaxDynamicSharedMemorySize,
                             GEMM_SMEM);
        cudaFuncSetAttribute(prep_fused_kernel, cudaFuncAttributeMaxDynamicSharedMemorySize,
                             PREP_SMEM);
        smem_set = 1;
    }

    prepA_kernel<<<(COUT * KDIM + 255) / 256, 256>>>(bk);
    prep_fused_kernel<<<dim3(L_ / 64, B_), 512, PREP_SMEM>>>(x, cw, cb);
    gemm_kernel<<<dim3(L_ / 128, COUT / 128, B_), 256, GEMM_SMEM>>>(bb, out);
}

// round 16
// speedup vs baseline: 3.1296x; 1.0019x over previous
#include <cuda_runtime.h>
#include <cuda_fp16.h>
#include <cstdint>
#include <math.h>

#define B_    16
#define CIN   256
#define COUT  256
#define L_    4096
#define LP2   (L_ + 2)          // 2 leading zero rows (causal pad)
#define NR    5
#define KDIM  3840              // NR * 3 * CIN (halves)
#define BL    (B_ * L_)

// ---------------- scratch (device globals; allocation-free) ----------------
__device__ float  g_fr[NR * BL];                                 // fr[n][b*L+l]
__device__ __align__(16) __half g_Ah[COUT * KDIM];               // [o][(n*3+k)*256+c]
__device__ __align__(16) __half g_xth[(size_t)B_ * LP2 * CIN];   // [b][l+2][c] = half(x)

// ---------------- helpers ----------------
__device__ __forceinline__ void cp16(uint32_t dst, const void* src) {
    asm volatile("cp.async.cg.shared.global [%0], [%1], 16;" :: "r"(dst), "l"(src));
}
__device__ __forceinline__ void cp_commit() { asm volatile("cp.async.commit_group;"); }
__device__ __forceinline__ void ldsm4(uint32_t* r, uint32_t addr) {
    asm volatile("ldmatrix.sync.aligned.m8n8.x4.shared.b16 {%0,%1,%2,%3}, [%4];"
                 : "=r"(r[0]), "=r"(r[1]), "=r"(r[2]), "=r"(r[3]) : "r"(addr));
}
__device__ __forceinline__ void mma_f16(float* d, const uint32_t* a, uint32_t b0, uint32_t b1) {
    asm volatile("mma.sync.aligned.m16n8k16.row.col.f32.f16.f16.f32 "
                 "{%0,%1,%2,%3}, {%4,%5,%6,%7}, {%8,%9}, {%0,%1,%2,%3};"
                 : "+f"(d[0]), "+f"(d[1]), "+f"(d[2]), "+f"(d[3])
                 : "r"(a[0]), "r"(a[1]), "r"(a[2]), "r"(a[3]), "r"(b0), "r"(b1));
}

// ---------------------------------------------------------------------------
// prep A: g_Ah[o][(n*3+k)*256 + c] = half(bk[n][o][c][k])
// ---------------------------------------------------------------------------
__global__ void __launch_bounds__(256) prepA_kernel(const float* __restrict__ w) {
    int i = blockIdx.x * 256 + threadIdx.x;
    if (i >= COUT * KDIM) return;
    const int o = i / KDIM;
    const int t = i - o * KDIM;
    const int n = t / 768;
    const int rem = t - n * 768;
    const int k = rem >> 8;
    const int c = rem & 255;
    g_Ah[i] = __float2half_rn(w[((n * COUT + o) * CIN + c) * 3 + k]);
}

// ---------------------------------------------------------------------------
// FUSED prep (512 threads, 2 rounds of 128 channels): transpose + controller
// ---------------------------------------------------------------------------
#define PREP_SW    (768 * NR)
#define PREP_XS    (128 * 66)
#define PREP_PART  (8 * 64 * NR)
#define PREP_SMEM  ((PREP_SW + PREP_XS + PREP_PART) * 4)

__global__ void __launch_bounds__(512) prep_fused_kernel(
    const float* __restrict__ x, const float* __restrict__ cw,
    const float* __restrict__ cb)
{
    extern __shared__ float psm[];
    float* sw   = psm;
    float* xs   = sw + PREP_SW;
    float* part = xs + PREP_XS;

    const int tid = threadIdx.x;
    const int l0  = blockIdx.x * 64;
    const int b   = blockIdx.y;

    for (int i = tid; i < PREP_SW; i += 512) sw[i] = cw[i];

    const int lt = tid & 63;
    const int cg = tid >> 6;
    float acc[NR];
#pragma unroll
    for (int n = 0; n < NR; n++) acc[n] = 0.0f;

#pragma unroll
    for (int cc = 0; cc < 2; cc++) {
        __syncthreads();
        for (int i = tid; i < 128 * 66; i += 512) {
            const int c = i / 66, j = i - c * 66;
            const int gl = l0 - 2 + j;
            xs[c * 66 + j] = (gl >= 0)
                ? x[((size_t)(b * CIN + cc * 128 + c)) * L_ + gl] : 0.0f;
        }
        __syncthreads();

        for (int i = tid; i < 64 * 64; i += 512) {
            const int l = i >> 6, c2 = i & 63;
            __half2 h = __floats2half2_rn(xs[(2 * c2) * 66 + l + 2],
                                          xs[(2 * c2 + 1) * 66 + l + 2]);
            *reinterpret_cast<__half2*>(
                &g_xth[((size_t)b * LP2 + 2 + l0 + l) * CIN + cc * 128 + 2 * c2]) = h;
        }

#pragma unroll
        for (int ci = 0; ci < 16; ci++) {
            const int c  = cg * 16 + ci;
            const int gc = cc * 128 + c;
            const float x0 = xs[c * 66 + lt];
            const float x1 = xs[c * 66 + lt + 1];
            const float x2 = xs[c * 66 + lt + 2];
            const float* w0 = &sw[gc * 3 * NR];
#pragma unroll
            for (int n = 0; n < NR; n++)
                acc[n] += x0 * w0[n] + x1 * w0[NR + n] + x2 * w0[2 * NR + n];
        }
    }

#pragma unroll
    for (int n = 0; n < NR; n++) part[(cg * 64 + lt) * NR + n] = acc[n];
    __syncthreads();

    if (tid < 64) {
        const int l = tid;
        float s[NR];
#pragma unroll
        for (int n = 0; n < NR; n++) {
            float t = __ldg(&cb[n]);
#pragma unroll
            for (int g = 0; g < 8; g++) t += part[(g * 64 + l) * NR + n];
            s[n] = t;
        }
        float mx = s[0];
#pragma unroll
        for (int n = 1; n < NR; n++) mx = fmaxf(mx, s[n]);
        float e[NR], sum = 0.0f;
#pragma unroll
        for (int n = 0; n < NR; n++) { e[n] = __expf(s[n] - mx); sum += e[n]; }
        const float inv = 1.0f / sum;
        const size_t bl = (size_t)b * L_ + l0 + l;
#pragma unroll
        for (int n = 0; n < NR; n++) g_fr[(size_t)n * BL + bl] = e[n] * inv;
    }

    if (blockIdx.x == 0 && tid < 256) {
        const int r = tid >> 7, c2 = tid & 127;
        *reinterpret_cast<__half2*>(
            &g_xth[((size_t)b * LP2 + r) * CIN + 2 * c2]) = __floats2half2_rn(0.f, 0.f);
    }
}

// ---------------------------------------------------------------------------
// fp16 GEMM, main loop manually unrolled by NST=3 so stage bases are
// compile-time constants (kills the IMAD address recomputation; alu -> ~6%).
// ---------------------------------------------------------------------------
#define BK     64
#define NTILE  60
#define A_BYT  (128 * 128)
#define B_BYT  (128 * 128)
#define STAGEB (A_BYT + B_BYT)
#define NST    3

__global__ void __launch_bounds__(256, 2) gemm_kernel(
    const float* __restrict__ bias,     // (NR, COUT)
    float* __restrict__ out)            // (B, COUT, L)
{
    extern __shared__ char smem[];
    const uint32_t sb = (uint32_t)__cvta_generic_to_shared(smem);
    float* sfr = reinterpret_cast<float*>(smem + NST * STAGEB);   // [NR][128]

    const int tid  = threadIdx.x;
    const int lane = tid & 31;
    const int wid  = tid >> 5;
    const int warp_m = wid >> 2;
    const int warp_n = wid & 3;

    const int b  = blockIdx.z;
    const int o0 = blockIdx.y * 128;
    const int l0 = blockIdx.x * 128;

    for (int i = tid; i < NR * 128; i += 256) {
        const int n = i >> 7, j = i & 127;
        sfr[i] = g_fr[(size_t)n * BL + (size_t)b * L_ + l0 + j];
    }

    const __half* Xt0 = g_xth + ((size_t)b * LP2 + l0) * CIN;

    // loader coords hoisted once
    const int ldrow = tid >> 3;                 // 0..31 (stride 32 over i)
    const int ldc   = tid & 7;
    const uint32_t ldoff = (uint32_t)(ldrow * 128 + ((ldc ^ (ldrow & 7)) * 16));
    // rows advance by 32 per i; (row&7) invariant under +32
    const size_t a_gstep = (size_t)32 * KDIM;
    const size_t b_gstep = (size_t)32 * CIN;

    auto load_tile = [&](int it, uint32_t sA) {
        const int n = it / 12;
        const int r = it - 12 * n;
        const int k = r >> 2;
        const int c0q = (r & 3) * 64;
        const __half* Ag = g_Ah + (size_t)o0 * KDIM + (size_t)it * BK
                         + (size_t)ldrow * KDIM + ldc * 8;
        const __half* Bg = Xt0 + (size_t)k * CIN + c0q
                         + (size_t)ldrow * CIN + ldc * 8;
        const uint32_t sB = sA + A_BYT;
#pragma unroll
        for (int i = 0; i < 4; i++) {
            cp16(sA + ldoff + (uint32_t)i * (32 * 128), Ag + (size_t)i * a_gstep);
            cp16(sB + ldoff + (uint32_t)i * (32 * 128), Bg + (size_t)i * b_gstep);
        }
        cp_commit();
    };

    float acc[4][4][4];
#pragma unroll
    for (int mt = 0; mt < 4; mt++)
#pragma unroll
        for (int ng = 0; ng < 4; ng++)
#pragma unroll
            for (int r = 0; r < 4; r++) acc[mt][ng][r] = 0.0f;

    load_tile(0, sb + 0 * STAGEB);
    load_tile(1, sb + 1 * STAGEB);

    // fragment addressing, hoisted
    const int acsel = lane >> 4;
    const int bcsel = (lane >> 3) & 1;
    const int frcol = warp_n * 32 + (lane >> 2);
    uint32_t aoff[4]; int r7a[4];
#pragma unroll
    for (int mt = 0; mt < 4; mt++) {
        const int row = warp_m * 64 + (lane & 15) + mt * 16;
        aoff[mt] = (uint32_t)(row * 128);
        r7a[mt]  = row & 7;
    }
    uint32_t boff[2]; int r7b[2];
#pragma unroll
    for (int g2 = 0; g2 < 2; g2++) {
        const int row = warp_n * 32 + (lane & 7) + ((lane >> 4) << 3) + g2 * 16;
        boff[g2] = (uint32_t)(row * 128);
        r7b[g2]  = row & 7;
    }

    __half2 frh[4];

    // one unrolled step; S is a compile-time stage constant
#define GEMM_STEP(S, IT, RELOAD)                                              \
    do {                                                                      \
        asm volatile("cp.async.wait_group 1;");                               \
        __syncthreads();                                                      \
        if ((IT) + 2 < NTILE) load_tile((IT) + 2, sb + (((S) + 2) % NST) * STAGEB); \
        else cp_commit();                                                     \
        if (RELOAD) {                                                         \
            const int n_ = (IT) / 12;                                         \
            _Pragma("unroll")                                                 \
            for (int q = 0; q < 4; q++)                                       \
                frh[q] = __half2half2(__float2half_rn(sfr[n_ * 128 + frcol + q * 8])); \
        }                                                                     \
        const uint32_t sA_ = sb + (S) * STAGEB;                               \
        const uint32_t sB_ = sA_ + A_BYT;                                     \
        _Pragma("unroll")                                                     \
        for (int ks = 0; ks < 4; ks++) {                                      \
            uint32_t a_[4][4];                                                \
            _Pragma("unroll")                                                 \
            for (int mt = 0; mt < 4; mt++)                                    \
                ldsm4(a_[mt], sA_ + aoff[mt] +                                \
                      (uint32_t)(((ks * 2 + acsel) ^ r7a[mt]) * 16));         \
            uint32_t bb_[2][4];                                               \
            _Pragma("unroll")                                                 \
            for (int g2 = 0; g2 < 2; g2++)                                    \
                ldsm4(bb_[g2], sB_ + boff[g2] +                               \
                      (uint32_t)(((ks * 2 + bcsel) ^ r7b[g2]) * 16));         \
            _Pragma("unroll")                                                 \
            for (int g2 = 0; g2 < 2; g2++)                                    \
                _Pragma("unroll")                                             \
                for (int j = 0; j < 4; j++) {                                 \
                    __half2 v_ = *reinterpret_cast<__half2*>(&bb_[g2][j]);    \
                    v_ = __hmul2(v_, frh[2 * g2 + (j >> 1)]);                 \
                    bb_[g2][j] = *reinterpret_cast<uint32_t*>(&v_);           \
                }                                                             \
            _Pragma("unroll")                                                 \
            for (int mt = 0; mt < 4; mt++)                                    \
                _Pragma("unroll")                                             \
                for (int g2 = 0; g2 < 2; g2++) {                              \
                    mma_f16(acc[mt][2 * g2],     a_[mt], bb_[g2][0], bb_[g2][1]); \
                    mma_f16(acc[mt][2 * g2 + 1], a_[mt], bb_[g2][2], bb_[g2][3]); \
                }                                                             \
        }                                                                     \
    } while (0)

    // NTILE = 60 = 3 * 20; rule boundaries (it % 12 == 0) land on slot 0 only
    for (int itb = 0; itb < NTILE; itb += 3) {
        const bool rb = (itb % 12) == 0;
        GEMM_STEP(0, itb + 0, rb);
        GEMM_STEP(1, itb + 1, false);
        GEMM_STEP(2, itb + 2, false);
    }
#undef GEMM_STEP

    // epilogue: out[o,l] = acc + sum_n fr[n,l] * bias[n,o]
    const int obase = o0 + warp_m * 64 + (lane >> 2);
    const int lloc0 = warp_n * 32 + (lane & 3) * 2;
    float* ob = out + ((size_t)b * COUT) * L_ + l0;

#pragma unroll
    for (int mt = 0; mt < 4; mt++) {
        const int o1 = obase + mt * 16;
        const int o2 = o1 + 8;
        float b1[NR], b2[NR];
#pragma unroll
        for (int n = 0; n < NR; n++) {
            b1[n] = __ldg(&bias[n * COUT + o1]);
            b2[n] = __ldg(&bias[n * COUT + o2]);
        }
#pragma unroll
        for (int ng = 0; ng < 4; ng++) {
            const int lloc = lloc0 + ng * 8;
            float t00 = 0.f, t01 = 0.f, t10 = 0.f, t11 = 0.f;
#pragma unroll
            for (int n = 0; n < NR; n++) {
                const float f0 = sfr[n * 128 + lloc];
                const float f1 = sfr[n * 128 + lloc + 1];
                t00 += f0 * b1[n]; t01 += f1 * b1[n];
                t10 += f0 * b2[n]; t11 += f1 * b2[n];
            }
            float2* p0 = reinterpret_cast<float2*>(ob + (size_t)o1 * L_ + lloc);
            float2* p1 = reinterpret_cast<float2*>(ob + (size_t)o2 * L_ + lloc);
            *p0 = make_float2(acc[mt][ng][0] + t00, acc[mt][ng][1] + t01);
            *p1 = make_float2(acc[mt][ng][2] + t10, acc[mt][ng][3] + t11);
        }
    }
}

#define GEMM_SMEM (NST * STAGEB + NR * 128 * 4)

// ---------------------------------------------------------------------------
// launch
// ---------------------------------------------------------------------------
extern "C" void kernel_launch(void* const* d_in, const int* in_sizes, int n_in,
                              void* d_out, int out_size) {
    const float* x  = (const float*)d_in[0];
    const float* bk = (const float*)d_in[1];
    const float* bb = (const float*)d_in[2];
    const float* cw = (const float*)d_in[3];
    const float* cb = (const float*)d_in[4];
    float* out = (float*)d_out;

    static int smem_set = 0;
    if (!smem_set) {
        cudaFuncSetAttribute(gemm_kernel, cudaFuncAttributeMaxDynamicSharedMemorySize,
                             GEMM_SMEM);
        cudaFuncSetAttribute(prep_fused_kernel, cudaFuncAttributeMaxDynamicSharedMemorySize,
                             PREP_SMEM);
        smem_set = 1;
    }

    prepA_kernel<<<(COUT * KDIM + 255) / 256, 256>>>(bk);
    prep_fused_kernel<<<dim3(L_ / 64, B_), 512, PREP_SMEM>>>(x, cw, cb);
    gemm_kernel<<<dim3(L_ / 128, COUT / 128, B_), 256, GEMM_SMEM>>>(bb, out);
}